// round 13
// baseline (speedup 1.0000x reference)
#include <cuda_runtime.h>
#include <cuda_fp16.h>
#include <math.h>
#include <stdint.h>

#define LSEQ 256
#define BB   64
#define DD   1024
#define HH   512
#define CC   6
#define NTOT 16384
#define DHE  1536
#define WINR 10
#define WSZ  21
#define HA4_COLS 2048
#define MTILES 129
#define CATK 1024
#define PRN  768

// ---------------- scratch ----------------
__device__ __align__(256) float g_PR  [(size_t)NTOT * PRN];
__device__ __align__(256) float g_EW  [(size_t)BB * LSEQ * WSZ];
__device__ __align__(256) float g_cat [(size_t)NTOT * HH];
__device__ __align__(256) float g_S   [(size_t)BB * LSEQ * LSEQ];
__device__ __align__(256) float g_HID [(size_t)NTOT * HH];
__device__ __align__(256) float g_bias768[PRN];
// fp16
__device__ __align__(256) __half g_xh  [(size_t)NTOT * DD];
__device__ __align__(256) __half g_HA4h[(size_t)NTOT * HA4_COLS];
__device__ __align__(256) __half g_cath[(size_t)NTOT * CATK];
__device__ __align__(256) __half g_emh [(size_t)NTOT * DHE];
__device__ __align__(256) __half g_XTh [(size_t)NTOT * DHE];
__device__ __align__(256) __half g_Sh  [(size_t)BB * LSEQ * LSEQ];
__device__ __align__(256) __half g_ATTh[(size_t)NTOT * DHE];
__device__ __align__(256) __half g_Wprh [(size_t)DD * PRN];
__device__ __align__(256) __half g_Wrelh[(size_t)8 * DD * HH];
__device__ __align__(256) __half g_Wcath[(size_t)CATK * HH];
__device__ __align__(256) __half g_Wmh  [(size_t)DHE * DHE];
__device__ __align__(256) __half g_Wlinh[(size_t)DHE * HH];

__device__ int g_cnt[2], g_cnt2[2], g_meta[4], g_idx[MTILES * 128];

__device__ __forceinline__ void cp16(uint32_t d, const void* s) {
    asm volatile("cp.async.cg.shared.global [%0], [%1], 16;" :: "r"(d), "l"(s));
}
__device__ __forceinline__ void ldm4(uint32_t* r, uint32_t a) {
    asm volatile("ldmatrix.sync.aligned.m8n8.x4.shared.b16 {%0,%1,%2,%3}, [%4];"
                 : "=r"(r[0]), "=r"(r[1]), "=r"(r[2]), "=r"(r[3]) : "r"(a));
}
__device__ __forceinline__ void ldm4t(uint32_t* r, uint32_t a) {
    asm volatile("ldmatrix.sync.aligned.m8n8.x4.trans.shared.b16 {%0,%1,%2,%3}, [%4];"
                 : "=r"(r[0]), "=r"(r[1]), "=r"(r[2]), "=r"(r[3]) : "r"(a));
}
__device__ __forceinline__ void mma16816(float* c, const uint32_t* a, const uint32_t* b) {
    asm volatile("mma.sync.aligned.m16n8k16.row.col.f32.f16.f16.f32 "
        "{%0,%1,%2,%3}, {%4,%5,%6,%7}, {%8,%9}, {%0,%1,%2,%3};"
        : "+f"(c[0]), "+f"(c[1]), "+f"(c[2]), "+f"(c[3])
        : "r"(a[0]), "r"(a[1]), "r"(a[2]), "r"(a[3]), "r"(b[0]), "r"(b[1]));
}

// ================= hgemm (128x128, BK=32, 5-stage) — used for S / ATT =================
#define HAP  40
#define HBPK 136
#define HSTG 5120
#define HNST 5
#define HSMEM (2 * HNST * HSTG * 2)

template<bool BT>
__device__ __forceinline__ void slab_h(uint32_t ab, uint32_t bb, int wm, int wn,
                                       int lane, float acc[4][4][4])
{
    const int lr = lane & 15;
    const int lc = (lane >> 4) << 3;
    #pragma unroll
    for (int ks = 0; ks < 32; ks += 16) {
        uint32_t af[4][4], bf[4][2];
        #pragma unroll
        for (int mt = 0; mt < 4; mt++)
            ldm4(af[mt], ab + (uint32_t)(((wm * 64 + mt * 16 + lr) * HAP + ks + lc) * 2));
        #pragma unroll
        for (int np = 0; np < 2; np++) {
            uint32_t r[4];
            if (!BT)
                ldm4t(r, bb + (uint32_t)(((ks + lr) * HBPK + wn * 32 + np * 16 + lc) * 2));
            else
                ldm4(r, bb + (uint32_t)(((wn * 32 + np * 16 + (lane >> 4) * 8 + (lane & 7)) * HAP
                                          + ks + (lane & 8)) * 2));
            bf[2*np][0]   = r[0]; bf[2*np][1]   = r[1];
            bf[2*np+1][0] = r[2]; bf[2*np+1][1] = r[3];
        }
        #pragma unroll
        for (int mt = 0; mt < 4; mt++)
            #pragma unroll
            for (int nt = 0; nt < 4; nt++)
                mma16816(acc[mt][nt], af[mt], bf[nt]);
    }
}

template<int ACT, bool BT, bool BIAS, bool WF, bool WH>
__global__ __launch_bounds__(256, 2) void hgemm(
    const __half* __restrict__ A, const __half* __restrict__ B,
    float* __restrict__ Cf, __half* __restrict__ Ch, const float* __restrict__ bias,
    int K, int lda, int ldb, int ldcf, int ldch,
    long long zA, long long zB, long long zC)
{
    A += (long long)blockIdx.z * zA;
    B += (long long)blockIdx.z * zB;
    if (WF) Cf += (long long)blockIdx.z * zC;
    if (WH) Ch += (long long)blockIdx.z * zC;

    extern __shared__ __half smh[];
    const uint32_t asb = (uint32_t)__cvta_generic_to_shared(smh);
    const uint32_t bsb = (uint32_t)__cvta_generic_to_shared(smh + HNST * HSTG);

    const int tid = threadIdx.x, lane = tid & 31, wid = tid >> 5;
    const int wm = wid & 1, wn = wid >> 1, g = lane >> 2, t = lane & 3;
    const int m0 = blockIdx.y * 128, n0 = blockIdx.x * 128;

    const int ar = tid >> 1, ac = (tid & 1) * 16;
    const int bkr = tid >> 4, bnc = (tid & 15) * 8;

    float acc[4][4][4];
    #pragma unroll
    for (int i = 0; i < 4; i++)
        #pragma unroll
        for (int j = 0; j < 4; j++)
            #pragma unroll
            for (int e = 0; e < 4; e++) acc[i][j][e] = 0.f;

    const int KT = K / 32;
    auto fill = [&](int s, int k0) {
        const uint32_t ab = asb + (uint32_t)(s * HSTG * 2);
        cp16(ab + (ar * HAP + ac) * 2,     A + (long long)(m0 + ar) * lda + k0 + ac);
        cp16(ab + (ar * HAP + ac + 8) * 2, A + (long long)(m0 + ar) * lda + k0 + ac + 8);
        const uint32_t bb = bsb + (uint32_t)(s * HSTG * 2);
        if (!BT) {
            cp16(bb + (bkr * HBPK + bnc) * 2,        B + (long long)(k0 + bkr) * ldb + n0 + bnc);
            cp16(bb + ((bkr + 16) * HBPK + bnc) * 2, B + (long long)(k0 + bkr + 16) * ldb + n0 + bnc);
        } else {
            cp16(bb + (ar * HAP + ac) * 2,     B + (long long)(n0 + ar) * ldb + k0 + ac);
            cp16(bb + (ar * HAP + ac + 8) * 2, B + (long long)(n0 + ar) * ldb + k0 + ac + 8);
        }
    };

    fill(0, 0);   asm volatile("cp.async.commit_group;");
    fill(1, 32);  asm volatile("cp.async.commit_group;");
    fill(2, 64);  asm volatile("cp.async.commit_group;");
    fill(3, 96);  asm volatile("cp.async.commit_group;");

    int s = 0, sp = 4;
    for (int kt = 0; kt < KT; kt++) {
        asm volatile("cp.async.wait_group 3;" ::: "memory");
        __syncthreads();
        if (kt + 4 < KT) fill(sp, (kt + 4) * 32);
        asm volatile("cp.async.commit_group;");
        slab_h<BT>(asb + (uint32_t)((s * HSTG) * 2),
                   bsb + (uint32_t)((s * HSTG) * 2), wm, wn, lane, acc);
        if (++s == HNST) s = 0;
        if (++sp == HNST) sp = 0;
    }

    #pragma unroll
    for (int mt = 0; mt < 4; mt++)
        #pragma unroll
        for (int nt = 0; nt < 4; nt++) {
            const int col = n0 + wn * 32 + nt * 8 + t * 2;
            #pragma unroll
            for (int half = 0; half < 2; half++) {
                const long long row = m0 + wm * 64 + mt * 16 + g + half * 8;
                float v0 = acc[mt][nt][half * 2 + 0];
                float v1 = acc[mt][nt][half * 2 + 1];
                if (BIAS) { v0 += bias[col]; v1 += bias[col + 1]; }
                if (ACT == 1) { v0 = fmaxf(v0, 0.f); v1 = fmaxf(v1, 0.f); }
                if (ACT == 2) { v0 = tanhf(v0); v1 = tanhf(v1); }
                if (WF) *(float2*)(Cf + row * ldcf + col) = make_float2(v0, v1);
                if (WH) {
                    __half2 h; h.x = __float2half(v0); h.y = __float2half(v1);
                    *(__half2*)(Ch + row * ldch + col) = h;
                }
            }
        }
}

// ================= hgemm2: 128x256 tile, BK=32, 5-stage, 1 CTA/SM =================
#define AP2   40
#define BPK2  264
#define ASTG2 5120      // halves
#define BSTG2 8448      // halves
#define NST2  5
#define HSMEM2 ((ASTG2 + BSTG2) * NST2 * 2)   // 135680

__device__ __forceinline__ void slab_h2(uint32_t ab, uint32_t bb, int wm, int wn,
                                        int lane, float acc[4][8][4])
{
    const int lr = lane & 15;
    const int lc = (lane >> 4) << 3;
    #pragma unroll
    for (int ks = 0; ks < 32; ks += 16) {
        uint32_t af[4][4], bf[8][2];
        #pragma unroll
        for (int mt = 0; mt < 4; mt++)
            ldm4(af[mt], ab + (uint32_t)(((wm * 64 + mt * 16 + lr) * AP2 + ks + lc) * 2));
        #pragma unroll
        for (int np = 0; np < 4; np++) {
            uint32_t r[4];
            ldm4t(r, bb + (uint32_t)(((ks + lr) * BPK2 + wn * 64 + np * 16 + lc) * 2));
            bf[2*np][0]   = r[0]; bf[2*np][1]   = r[1];
            bf[2*np+1][0] = r[2]; bf[2*np+1][1] = r[3];
        }
        #pragma unroll
        for (int mt = 0; mt < 4; mt++)
            #pragma unroll
            for (int nt = 0; nt < 8; nt++)
                mma16816(acc[mt][nt], af[mt], bf[nt]);
    }
}

template<int ACT, bool BIAS, bool WF, bool WH>
__global__ __launch_bounds__(256, 1) void hgemm2(
    const __half* __restrict__ A, const __half* __restrict__ B,
    float* __restrict__ Cf, __half* __restrict__ Ch, const float* __restrict__ bias,
    int K, int lda, int ldb, int ldcf, int ldch)
{
    extern __shared__ __half smh[];
    const uint32_t asb = (uint32_t)__cvta_generic_to_shared(smh);
    const uint32_t bsb = (uint32_t)__cvta_generic_to_shared(smh + NST2 * ASTG2);

    const int tid = threadIdx.x, lane = tid & 31, wid = tid >> 5;
    const int wm = wid & 1, wn = wid >> 1, g = lane >> 2, t = lane & 3;
    const int m0 = blockIdx.y * 128, n0 = blockIdx.x * 256;

    const int ar = tid >> 1, ac = (tid & 1) * 16;
    const int br = tid >> 3, bc = (tid & 7) * 32;

    float acc[4][8][4];
    #pragma unroll
    for (int i = 0; i < 4; i++)
        #pragma unroll
        for (int j = 0; j < 8; j++)
            #pragma unroll
            for (int e = 0; e < 4; e++) acc[i][j][e] = 0.f;

    const int KT = K / 32;
    auto fill = [&](int s, int k0) {
        const uint32_t ab = asb + (uint32_t)(s * ASTG2 * 2);
        cp16(ab + (ar * AP2 + ac) * 2,     A + (long long)(m0 + ar) * lda + k0 + ac);
        cp16(ab + (ar * AP2 + ac + 8) * 2, A + (long long)(m0 + ar) * lda + k0 + ac + 8);
        const uint32_t bb = bsb + (uint32_t)(s * BSTG2 * 2);
        const __half* bp = B + (long long)(k0 + br) * ldb + n0 + bc;
        #pragma unroll
        for (int c = 0; c < 4; c++)
            cp16(bb + (br * BPK2 + bc + c * 8) * 2, bp + c * 8);
    };

    fill(0, 0);   asm volatile("cp.async.commit_group;");
    fill(1, 32);  asm volatile("cp.async.commit_group;");
    fill(2, 64);  asm volatile("cp.async.commit_group;");
    fill(3, 96);  asm volatile("cp.async.commit_group;");

    int s = 0, sp = 4;
    for (int kt = 0; kt < KT; kt++) {
        asm volatile("cp.async.wait_group 3;" ::: "memory");
        __syncthreads();
        if (kt + 4 < KT) fill(sp, (kt + 4) * 32);
        asm volatile("cp.async.commit_group;");
        slab_h2(asb + (uint32_t)((s * ASTG2) * 2),
                bsb + (uint32_t)((s * BSTG2) * 2), wm, wn, lane, acc);
        if (++s == NST2) s = 0;
        if (++sp == NST2) sp = 0;
    }

    #pragma unroll
    for (int mt = 0; mt < 4; mt++)
        #pragma unroll
        for (int nt = 0; nt < 8; nt++) {
            const int col = n0 + wn * 64 + nt * 8 + t * 2;
            #pragma unroll
            for (int half = 0; half < 2; half++) {
                const long long row = m0 + wm * 64 + mt * 16 + g + half * 8;
                float v0 = acc[mt][nt][half * 2 + 0];
                float v1 = acc[mt][nt][half * 2 + 1];
                if (BIAS) { v0 += bias[col]; v1 += bias[col + 1]; }
                if (ACT == 1) { v0 = fmaxf(v0, 0.f); v1 = fmaxf(v1, 0.f); }
                if (WF) *(float2*)(Cf + row * ldcf + col) = make_float2(v0, v1);
                if (WH) {
                    __half2 h; h.x = __float2half(v0); h.y = __float2half(v1);
                    *(__half2*)(Ch + row * ldch + col) = h;
                }
            }
        }
}

// speaker-split relation GEMM on the 128x256 tile
__global__ __launch_bounds__(256, 1) void hgemm2_rel()
{
    const int M0 = g_meta[0], M0pad = g_meta[1], M1 = g_meta[2], M1pad = g_meta[3];
    const int m0 = blockIdx.y * 128;
    if (m0 >= M0pad + M1pad) return;
    const int grp = (m0 < M0pad) ? 0 : 1;
    const int n0 = blockIdx.x * 256, j = blockIdx.z;

    extern __shared__ __half smh[];
    __shared__ int sidx[128];
    const uint32_t asb = (uint32_t)__cvta_generic_to_shared(smh);
    const uint32_t bsb = (uint32_t)__cvta_generic_to_shared(smh + NST2 * ASTG2);

    const int tid = threadIdx.x, lane = tid & 31, wid = tid >> 5;
    const int wm = wid & 1, wn = wid >> 1, g = lane >> 2, t = lane & 3;

    if (tid < 128) sidx[tid] = g_idx[m0 + tid];

    const int ar = tid >> 1, ac = (tid & 1) * 16;
    const int br = tid >> 3, bc = (tid & 7) * 32;
    const __half* Arow = g_xh + (long long)g_idx[m0 + ar] * DD;
    const __half* B = g_Wrelh + (long long)(grp * 4 + j) * DD * HH;

    float acc[4][8][4];
    #pragma unroll
    for (int i = 0; i < 4; i++)
        #pragma unroll
        for (int jj = 0; jj < 8; jj++)
            #pragma unroll
            for (int e = 0; e < 4; e++) acc[i][jj][e] = 0.f;

    auto fill = [&](int s, int k0) {
        const uint32_t ab = asb + (uint32_t)(s * ASTG2 * 2);
        cp16(ab + (ar * AP2 + ac) * 2,     Arow + k0 + ac);
        cp16(ab + (ar * AP2 + ac + 8) * 2, Arow + k0 + ac + 8);
        const uint32_t bb = bsb + (uint32_t)(s * BSTG2 * 2);
        const __half* bp = B + (long long)(k0 + br) * HH + n0 + bc;
        #pragma unroll
        for (int c = 0; c < 4; c++)
            cp16(bb + (br * BPK2 + bc + c * 8) * 2, bp + c * 8);
    };

    fill(0, 0);   asm volatile("cp.async.commit_group;");
    fill(1, 32);  asm volatile("cp.async.commit_group;");
    fill(2, 64);  asm volatile("cp.async.commit_group;");
    fill(3, 96);  asm volatile("cp.async.commit_group;");

    const int KT = DD / 32;
    int s = 0, sp = 4;
    for (int kt = 0; kt < KT; kt++) {
        asm volatile("cp.async.wait_group 3;" ::: "memory");
        __syncthreads();
        if (kt + 4 < KT) fill(sp, (kt + 4) * 32);
        asm volatile("cp.async.commit_group;");
        slab_h2(asb + (uint32_t)((s * ASTG2) * 2),
                bsb + (uint32_t)((s * BSTG2) * 2), wm, wn, lane, acc);
        if (++s == NST2) s = 0;
        if (++sp == NST2) sp = 0;
    }

    #pragma unroll
    for (int mt = 0; mt < 4; mt++)
        #pragma unroll
        for (int nt = 0; nt < 8; nt++) {
            const int col = j * HH + n0 + wn * 64 + nt * 8 + t * 2;
            #pragma unroll
            for (int half = 0; half < 2; half++) {
                const int lr = wm * 64 + mt * 16 + g + half * 8;
                const int pr = m0 + lr;
                const bool valid = (grp == 0) ? (pr < M0) : (pr - M0pad < M1);
                if (valid) {
                    __half2 h;
                    h.x = __float2half(acc[mt][nt][half * 2]);
                    h.y = __float2half(acc[mt][nt][half * 2 + 1]);
                    *(__half2*)(g_HA4h + (long long)sidx[lr] * HA4_COLS + col) = h;
                }
            }
        }
}

// ================= glue =================
__global__ void part_count(const int* __restrict__ sp)
{
    const int n = blockIdx.x * blockDim.x + threadIdx.x;
    if (n < MTILES * 128) g_idx[n] = 0;
    if (n < NTOT) atomicAdd(&g_cnt[sp[(n & 255) * BB + (n >> 8)]], 1);
}
__global__ void part_meta()
{
    const int M0 = g_cnt[0], M1 = g_cnt[1];
    g_meta[0] = M0; g_meta[1] = ((M0 + 127) / 128) * 128;
    g_meta[2] = M1; g_meta[3] = ((M1 + 127) / 128) * 128;
    g_cnt[0] = g_cnt[1] = g_cnt2[0] = g_cnt2[1] = 0;
}
__global__ void part_assign(const int* __restrict__ sp)
{
    const int n = blockIdx.x * blockDim.x + threadIdx.x;
    if (n >= NTOT) return;
    const int s = sp[(n & 255) * BB + (n >> 8)];
    const int slot = atomicAdd(&g_cnt2[s], 1);
    g_idx[(s == 0) ? slot : g_meta[1] + slot] = n;
}
__global__ void f2h_kernel(const float* __restrict__ s, __half* __restrict__ d, int n)
{
    int i = (blockIdx.x * blockDim.x + threadIdx.x) * 4;
    if (i + 3 < n) {
        float4 v = *(const float4*)(s + i);
        __half2 a, b;
        a.x = __float2half(v.x); a.y = __float2half(v.y);
        b.x = __float2half(v.z); b.y = __float2half(v.w);
        *(__half2*)(d + i) = a;
        *(__half2*)(d + i + 2) = b;
    }
}
__global__ void make_x_kernel(const float* __restrict__ f)
{
    const int n = blockIdx.x, b = n >> 8, s = n & 255;
    const float* src = f + ((long long)s * BB + b) * DD;
    for (int d = threadIdx.x; d < DD; d += blockDim.x) {
        const __half h = __float2half(src[d]);
        g_emh[(long long)n * DHE + d] = h;
        g_xh [(long long)n * DD  + d] = h;
    }
}
__global__ void build_wcat(const float* __restrict__ Wn, const float* __restrict__ Ws)
{
    const int i = blockIdx.x * blockDim.x + threadIdx.x;
    if (i < HH * HH) {
        g_Wcath[i] = __float2half(Wn[i]);
        g_Wcath[HH * HH + i] = __float2half(Ws[i]);
    }
}
__global__ void build_wpr(const float* __restrict__ Ws, const float* __restrict__ Wr,
                          const float* __restrict__ br)
{
    const int i = blockIdx.x * blockDim.x + threadIdx.x;
    if (i < DD * PRN) {
        const int d = i / PRN, c = i % PRN;
        g_Wprh[i] = __float2half((c < 256) ? Ws[d * 256 + c] : Wr[d * 512 + (c - 256)]);
    }
    if (i < PRN) g_bias768[i] = (i < 256) ? 0.f : br[i - 256];
}
__global__ __launch_bounds__(256) void edge_softmax_kernel()
{
    const int b = blockIdx.x;
    const int i = threadIdx.x;
    const float* Pb = g_PR + (long long)b * 256 * PRN;

    float m = -1e30f;
    for (int s = 0; s < LSEQ; s++)
        m = fmaxf(m, Pb[(long long)s * PRN + i]);

    float Z = 0.f;
    for (int s = 0; s < LSEQ; s++)
        Z += __expf(Pb[(long long)s * PRN + i] - m);

    float ew[WSZ];
    float Swin = 0.f;
    #pragma unroll
    for (int d = 0; d < WSZ; d++) {
        const int s = i - WINR + d;
        float e = 0.f;
        if (s >= 0 && s < LSEQ) {
            e = __expf(Pb[(long long)s * PRN + i] - m);
            Swin += e;
        }
        ew[d] = e;
    }
    const float den = Swin + 1e-10f * (Z - Swin);
    float* dst = g_EW + ((long long)(b * 256 + i)) * WSZ;
    #pragma unroll
    for (int d = 0; d < WSZ; d++)
        dst[d] = ew[d] / den;
}
__global__ __launch_bounds__(512) void rgcn_agg_kernel(const int* __restrict__ sp)
{
    const int n = blockIdx.x, b = n >> 8, k = n & 255, h = threadIdx.x;
    __shared__ float w[WSZ];
    const int lo = max(k - WINR, 0), hi = min(k + WINR, LSEQ - 1);
    const int cnt = hi - lo + 1;
    if (h < cnt) {
        const int i = lo + h;
        w[h] = g_EW[((long long)(b * 256 + i)) * WSZ + (k - i + WINR)];
    }
    __syncthreads();
    const int spk = sp[k * BB + b];
    float acc = g_PR[(long long)n * PRN + 256 + h];
    for (int t = 0; t < cnt; t++) {
        const int i = lo + t;
        const int j = spk * 2 + ((i < k) ? 0 : 1);
        acc += w[t] * __half2float(g_HA4h[((long long)(b * 256 + i)) * HA4_COLS + j * HH + h]);
    }
    g_cat [(long long)n * HH + h] = acc;
    g_cath[(long long)n * CATK + HH + h] = __float2half(acc);
}
__global__ __launch_bounds__(512) void nbr_kernel()
{
    const int b = blockIdx.x, ks = blockIdx.y * 64, h = threadIdx.x;
    float run = 0.f;
    const int lo = max(ks - WINR, 0), hi = min(ks + WINR, LSEQ - 1);
    for (int j = lo; j <= hi; j++) run += g_cat[((long long)(b * 256 + j)) * HH + h];
    g_cath[((long long)(b * 256 + ks)) * CATK + h] = __float2half(run);
    for (int k = ks + 1; k < ks + 64; k++) {
        if (k + WINR < LSEQ) run += g_cat[((long long)(b * 256 + k + WINR)) * HH + h];
        if (k - WINR - 1 >= 0) run -= g_cat[((long long)(b * 256 + k - WINR - 1)) * HH + h];
        g_cath[((long long)(b * 256 + k)) * CATK + h] = __float2half(run);
    }
}
__global__ void softmax_rows_kernel()
{
    __shared__ float red[256];
    const long long r = blockIdx.x;
    const int s = threadIdx.x;
    const float v = g_S[r * 256 + s];
    red[s] = v; __syncthreads();
    for (int o = 128; o > 0; o >>= 1) { if (s < o) red[s] = fmaxf(red[s], red[s + o]); __syncthreads(); }
    const float m = red[0]; __syncthreads();
    const float e = __expf(v - m);
    red[s] = e; __syncthreads();
    for (int o = 128; o > 0; o >>= 1) { if (s < o) red[s] += red[s + o]; __syncthreads(); }
    g_Sh[r * 256 + s] = __float2half(e / red[0]);
}
__global__ void final_kernel(const float* __restrict__ W_fc,
                             const float* __restrict__ b_fc, float* __restrict__ out)
{
    const int gw = (blockIdx.x * blockDim.x + threadIdx.x) >> 5;
    const int lane = threadIdx.x & 31;
    if (gw >= NTOT) return;
    float p[CC] = {0.f, 0.f, 0.f, 0.f, 0.f, 0.f};
    #pragma unroll
    for (int j = 0; j < 16; j++) {
        const int hx = lane + j * 32;
        const float hv = g_HID[(long long)gw * HH + hx];
        const float* wr = W_fc + (long long)hx * CC;
        #pragma unroll
        for (int c = 0; c < CC; c++) p[c] += hv * wr[c];
    }
    #pragma unroll
    for (int o = 16; o > 0; o >>= 1)
        #pragma unroll
        for (int c = 0; c < CC; c++) p[c] += __shfl_down_sync(0xffffffffu, p[c], o);
    if (lane == 0) {
        float lg[CC], m = -1e30f;
        #pragma unroll
        for (int c = 0; c < CC; c++) { lg[c] = p[c] + b_fc[c]; m = fmaxf(m, lg[c]); }
        float ss = 0.f;
        #pragma unroll
        for (int c = 0; c < CC; c++) ss += __expf(lg[c] - m);
        const float lse = m + logf(ss);
        #pragma unroll
        for (int c = 0; c < CC; c++) out[(long long)gw * CC + c] = lg[c] - lse;
    }
}

// ================= host =================
extern "C" void kernel_launch(void* const* d_in, const int* in_sizes, int n_in,
                              void* d_out, int out_size)
{
    const float* features = (const float*)d_in[0];
    const float* Wscalar  = (const float*)d_in[1];
    const float* W_rel    = (const float*)d_in[2];
    const float* W_root   = (const float*)d_in[3];
    const float* b_rgcn   = (const float*)d_in[4];
    const float* W_nbr    = (const float*)d_in[5];
    const float* W_self   = (const float*)d_in[6];
    const float* b_gc     = (const float*)d_in[7];
    const float* W_match  = (const float*)d_in[8];
    const float* b_match  = (const float*)d_in[9];
    const float* W_lin    = (const float*)d_in[10];
    const float* b_lin    = (const float*)d_in[11];
    const float* W_fc     = (const float*)d_in[12];
    const float* b_fc     = (const float*)d_in[13];
    const int*   speakers = (const int*)  d_in[14];
    float* out = (float*)d_out;

    float *PR, *S, *HID, *b768;
    __half *xh, *emh, *cath, *XTh, *Sh, *ATTh, *Wprh, *Wrelh, *Wcath, *Wmh, *Wlinh;
    cudaGetSymbolAddress((void**)&PR,  g_PR);
    cudaGetSymbolAddress((void**)&S,   g_S);
    cudaGetSymbolAddress((void**)&HID, g_HID);
    cudaGetSymbolAddress((void**)&b768,g_bias768);
    cudaGetSymbolAddress((void**)&xh,  g_xh);
    cudaGetSymbolAddress((void**)&emh, g_emh);
    cudaGetSymbolAddress((void**)&cath,g_cath);
    cudaGetSymbolAddress((void**)&XTh, g_XTh);
    cudaGetSymbolAddress((void**)&Sh,  g_Sh);
    cudaGetSymbolAddress((void**)&ATTh,g_ATTh);
    cudaGetSymbolAddress((void**)&Wprh, g_Wprh);
    cudaGetSymbolAddress((void**)&Wrelh,g_Wrelh);
    cudaGetSymbolAddress((void**)&Wcath,g_Wcath);
    cudaGetSymbolAddress((void**)&Wmh,  g_Wmh);
    cudaGetSymbolAddress((void**)&Wlinh,g_Wlinh);

    cudaFuncSetAttribute(hgemm2<0,true,true,false>, cudaFuncAttributeMaxDynamicSharedMemorySize, HSMEM2);
    cudaFuncSetAttribute(hgemm2<0,true,false,true>, cudaFuncAttributeMaxDynamicSharedMemorySize, HSMEM2);
    cudaFuncSetAttribute(hgemm2<1,true,true,false>, cudaFuncAttributeMaxDynamicSharedMemorySize, HSMEM2);
    cudaFuncSetAttribute(hgemm2_rel,                cudaFuncAttributeMaxDynamicSharedMemorySize, HSMEM2);
    cudaFuncSetAttribute(hgemm<2,true,false,true,false>, cudaFuncAttributeMaxDynamicSharedMemorySize, HSMEM);
    cudaFuncSetAttribute(hgemm<0,false,false,false,true>,cudaFuncAttributeMaxDynamicSharedMemorySize, HSMEM);

    cudaStream_t s2;
    cudaStreamCreateWithFlags(&s2, cudaStreamNonBlocking);
    cudaEvent_t e1, e2;
    cudaEventCreateWithFlags(&e1, cudaEventDisableTiming);
    cudaEventCreateWithFlags(&e2, cudaEventDisableTiming);

    // 0. prep
    make_x_kernel<<<NTOT, 256>>>(features);
    build_wcat<<<(HH*HH + 255)/256, 256>>>(W_nbr, W_self);
    build_wpr<<<(DD*PRN + 255)/256, 256>>>(Wscalar, W_root, b_rgcn);
    f2h_kernel<<<(8*DD*HH/4 + 255)/256, 256>>>(W_rel, Wrelh, 8*DD*HH);
    f2h_kernel<<<(DHE*DHE/4 + 255)/256, 256>>>(W_match, Wmh, DHE*DHE);
    f2h_kernel<<<(DHE*HH/4 + 255)/256, 256>>>(W_lin, Wlinh, DHE*HH);
    part_count<<<(MTILES*128 + 255)/256, 256>>>(speakers);
    part_meta<<<1, 1>>>();
    part_assign<<<(NTOT + 255)/256, 256>>>(speakers);

    // fork relation GEMM
    cudaEventRecord(e1, 0);
    cudaStreamWaitEvent(s2, e1, 0);
    hgemm2_rel<<<dim3(HH/256, MTILES, 4), 256, HSMEM2, s2>>>();
    cudaEventRecord(e2, s2);

    // 1. [P | root] = xh @ Wprh + [0|b_rgcn]
    hgemm2<0,true,true,false><<<dim3(PRN/256, NTOT/128), 256, HSMEM2>>>(
        xh, Wprh, PR, nullptr, b768, DD, DD, PRN, PRN, 0);

    // 2. edge softmax
    edge_softmax_kernel<<<BB, 256>>>();

    cudaStreamWaitEvent(0, e2, 0);

    // 3. RGCN aggregation; neighbor window
    rgcn_agg_kernel<<<NTOT, 512>>>(speakers);
    nbr_kernel<<<dim3(BB, LSEQ/64), 512>>>();

    // 4. h2 = cath @ Wcath + b_gc -> emh upper
    hgemm2<0,true,false,true><<<dim3(HH/256, NTOT/128), 256, HSMEM2>>>(
        cath, Wcath, nullptr, emh + DD, b_gc, CATK, CATK, HH, 0, DHE);

    // 5. XTh = emh @ Wmh + b_match
    hgemm2<0,true,false,true><<<dim3(DHE/256, NTOT/128), 256, HSMEM2>>>(
        emh, Wmh, nullptr, XTh, b_match, DHE, DHE, DHE, 0, DHE);

    // 6. S = tanh(XTh @ emh^T) batched; softmax
    hgemm<2,true,false,true,false><<<dim3(LSEQ/128, LSEQ/128, BB), 256, HSMEM>>>(
        XTh, emh, S, nullptr, nullptr, DHE, DHE, DHE, LSEQ, 0,
        (long long)LSEQ*DHE, (long long)LSEQ*DHE, (long long)LSEQ*LSEQ);
    softmax_rows_kernel<<<BB*LSEQ, 256>>>();

    // 7. ATTh = Sh @ emh
    hgemm<0,false,false,false,true><<<dim3(DHE/128, LSEQ/128, BB), 256, HSMEM>>>(
        Sh, emh, nullptr, ATTh, nullptr, LSEQ, LSEQ, DHE, 0, DHE,
        (long long)LSEQ*LSEQ, (long long)LSEQ*DHE, (long long)LSEQ*DHE);

    // 8. HID = relu(ATTh @ Wlinh + b_lin)
    hgemm2<1,true,true,false><<<dim3(HH/256, NTOT/128), 256, HSMEM2>>>(
        ATTh, Wlinh, HID, nullptr, b_lin, DHE, DHE, HH, HH, 0);

    // 9. output
    final_kernel<<<(NTOT*32 + 127)/128, 128>>>(W_fc, b_fc, out);
}

// round 14
// speedup vs baseline: 1.2028x; 1.2028x over previous
#include <cuda_runtime.h>
#include <cuda_fp16.h>
#include <math.h>
#include <stdint.h>

#define LSEQ 256
#define BB   64
#define DD   1024
#define HH   512
#define CC   6
#define NTOT 16384
#define DHE  1536
#define WINR 10
#define WSZ  21
#define HA4_COLS 2048
#define MTILES 129
#define CATK 1024
#define PRN  768

// ---------------- scratch ----------------
__device__ __align__(256) float g_PR  [(size_t)NTOT * PRN];
__device__ __align__(256) float g_EW  [(size_t)BB * LSEQ * WSZ];
__device__ __align__(256) float g_cat [(size_t)NTOT * HH];
__device__ __align__(256) float g_S   [(size_t)BB * LSEQ * LSEQ];
__device__ __align__(256) float g_HID [(size_t)NTOT * HH];
__device__ __align__(256) float g_bias768[PRN];
// fp16
__device__ __align__(256) __half g_xh  [(size_t)NTOT * DD];
__device__ __align__(256) __half g_HA4h[(size_t)NTOT * HA4_COLS];
__device__ __align__(256) __half g_cath[(size_t)NTOT * CATK];
__device__ __align__(256) __half g_emh [(size_t)NTOT * DHE];
__device__ __align__(256) __half g_XTh [(size_t)NTOT * DHE];
__device__ __align__(256) __half g_Sh  [(size_t)BB * LSEQ * LSEQ];
__device__ __align__(256) __half g_ATTh[(size_t)NTOT * DHE];
__device__ __align__(256) __half g_Wprh [(size_t)DD * PRN];
__device__ __align__(256) __half g_Wrelh[(size_t)8 * DD * HH];
__device__ __align__(256) __half g_Wcath[(size_t)CATK * HH];
__device__ __align__(256) __half g_Wmh  [(size_t)DHE * DHE];
__device__ __align__(256) __half g_Wlinh[(size_t)DHE * HH];

__device__ int g_cnt[2], g_cnt2[2], g_meta[4], g_idx[MTILES * 128];

__device__ __forceinline__ void cp16(uint32_t d, const void* s) {
    asm volatile("cp.async.cg.shared.global [%0], [%1], 16;" :: "r"(d), "l"(s));
}
__device__ __forceinline__ void ldm4(uint32_t* r, uint32_t a) {
    asm volatile("ldmatrix.sync.aligned.m8n8.x4.shared.b16 {%0,%1,%2,%3}, [%4];"
                 : "=r"(r[0]), "=r"(r[1]), "=r"(r[2]), "=r"(r[3]) : "r"(a));
}
__device__ __forceinline__ void ldm4t(uint32_t* r, uint32_t a) {
    asm volatile("ldmatrix.sync.aligned.m8n8.x4.trans.shared.b16 {%0,%1,%2,%3}, [%4];"
                 : "=r"(r[0]), "=r"(r[1]), "=r"(r[2]), "=r"(r[3]) : "r"(a));
}
__device__ __forceinline__ void mma16816(float* c, const uint32_t* a, const uint32_t* b) {
    asm volatile("mma.sync.aligned.m16n8k16.row.col.f32.f16.f16.f32 "
        "{%0,%1,%2,%3}, {%4,%5,%6,%7}, {%8,%9}, {%0,%1,%2,%3};"
        : "+f"(c[0]), "+f"(c[1]), "+f"(c[2]), "+f"(c[3])
        : "r"(a[0]), "r"(a[1]), "r"(a[2]), "r"(a[3]), "r"(b[0]), "r"(b[1]));
}

// ================= fp16 hgemm: 128x128 tile, BK=32, 5-stage =================
#define HAP  40
#define HBPK 136
#define HSTG 5120
#define HNST 5
#define HSMEM (2 * HNST * HSTG * 2)   // 102400

template<bool BT>
__device__ __forceinline__ void slab_h(uint32_t ab, uint32_t bb, int wm, int wn,
                                       int lane, float acc[4][4][4])
{
    const int lr = lane & 15;
    const int lc = (lane >> 4) << 3;
    #pragma unroll
    for (int ks = 0; ks < 32; ks += 16) {
        uint32_t af[4][4], bf[4][2];
        #pragma unroll
        for (int mt = 0; mt < 4; mt++)
            ldm4(af[mt], ab + (uint32_t)(((wm * 64 + mt * 16 + lr) * HAP + ks + lc) * 2));
        #pragma unroll
        for (int np = 0; np < 2; np++) {
            uint32_t r[4];
            if (!BT)
                ldm4t(r, bb + (uint32_t)(((ks + lr) * HBPK + wn * 32 + np * 16 + lc) * 2));
            else
                ldm4(r, bb + (uint32_t)(((wn * 32 + np * 16 + (lane >> 4) * 8 + (lane & 7)) * HAP
                                          + ks + (lane & 8)) * 2));
            bf[2*np][0]   = r[0]; bf[2*np][1]   = r[1];
            bf[2*np+1][0] = r[2]; bf[2*np+1][1] = r[3];
        }
        #pragma unroll
        for (int mt = 0; mt < 4; mt++)
            #pragma unroll
            for (int nt = 0; nt < 4; nt++)
                mma16816(acc[mt][nt], af[mt], bf[nt]);
    }
}

template<int ACT, bool BT, bool BIAS, bool WF, bool WH>
__global__ __launch_bounds__(256, 2) void hgemm(
    const __half* __restrict__ A, const __half* __restrict__ B,
    float* __restrict__ Cf, __half* __restrict__ Ch, const float* __restrict__ bias,
    int K, int lda, int ldb, int ldcf, int ldch,
    long long zA, long long zB, long long zC)
{
    A += (long long)blockIdx.z * zA;
    B += (long long)blockIdx.z * zB;
    if (WF) Cf += (long long)blockIdx.z * zC;
    if (WH) Ch += (long long)blockIdx.z * zC;

    extern __shared__ __half smh[];
    const uint32_t asb = (uint32_t)__cvta_generic_to_shared(smh);
    const uint32_t bsb = (uint32_t)__cvta_generic_to_shared(smh + HNST * HSTG);

    const int tid = threadIdx.x, lane = tid & 31, wid = tid >> 5;
    const int wm = wid & 1, wn = wid >> 1, g = lane >> 2, t = lane & 3;
    const int m0 = blockIdx.y * 128, n0 = blockIdx.x * 128;

    const int ar = tid >> 1, ac = (tid & 1) * 16;
    const int bkr = tid >> 4, bnc = (tid & 15) * 8;

    float acc[4][4][4];
    #pragma unroll
    for (int i = 0; i < 4; i++)
        #pragma unroll
        for (int j = 0; j < 4; j++)
            #pragma unroll
            for (int e = 0; e < 4; e++) acc[i][j][e] = 0.f;

    const int KT = K / 32;
    auto fill = [&](int s, int k0) {
        const uint32_t ab = asb + (uint32_t)(s * HSTG * 2);
        cp16(ab + (ar * HAP + ac) * 2,     A + (long long)(m0 + ar) * lda + k0 + ac);
        cp16(ab + (ar * HAP + ac + 8) * 2, A + (long long)(m0 + ar) * lda + k0 + ac + 8);
        const uint32_t bb = bsb + (uint32_t)(s * HSTG * 2);
        if (!BT) {
            cp16(bb + (bkr * HBPK + bnc) * 2,        B + (long long)(k0 + bkr) * ldb + n0 + bnc);
            cp16(bb + ((bkr + 16) * HBPK + bnc) * 2, B + (long long)(k0 + bkr + 16) * ldb + n0 + bnc);
        } else {
            cp16(bb + (ar * HAP + ac) * 2,     B + (long long)(n0 + ar) * ldb + k0 + ac);
            cp16(bb + (ar * HAP + ac + 8) * 2, B + (long long)(n0 + ar) * ldb + k0 + ac + 8);
        }
    };

    fill(0, 0);   asm volatile("cp.async.commit_group;");
    fill(1, 32);  asm volatile("cp.async.commit_group;");
    fill(2, 64);  asm volatile("cp.async.commit_group;");
    fill(3, 96);  asm volatile("cp.async.commit_group;");

    int s = 0, sp = 4;
    for (int kt = 0; kt < KT; kt++) {
        asm volatile("cp.async.wait_group 3;" ::: "memory");
        __syncthreads();
        if (kt + 4 < KT) fill(sp, (kt + 4) * 32);
        asm volatile("cp.async.commit_group;");
        slab_h<BT>(asb + (uint32_t)((s * HSTG) * 2),
                   bsb + (uint32_t)((s * HSTG) * 2), wm, wn, lane, acc);
        if (++s == HNST) s = 0;
        if (++sp == HNST) sp = 0;
    }

    #pragma unroll
    for (int mt = 0; mt < 4; mt++)
        #pragma unroll
        for (int nt = 0; nt < 4; nt++) {
            const int col = n0 + wn * 32 + nt * 8 + t * 2;
            #pragma unroll
            for (int half = 0; half < 2; half++) {
                const long long row = m0 + wm * 64 + mt * 16 + g + half * 8;
                float v0 = acc[mt][nt][half * 2 + 0];
                float v1 = acc[mt][nt][half * 2 + 1];
                if (BIAS) { v0 += bias[col]; v1 += bias[col + 1]; }
                if (ACT == 1) { v0 = fmaxf(v0, 0.f); v1 = fmaxf(v1, 0.f); }
                if (ACT == 2) { v0 = tanhf(v0); v1 = tanhf(v1); }
                if (WF) *(float2*)(Cf + row * ldcf + col) = make_float2(v0, v1);
                if (WH) {
                    __half2 h; h.x = __float2half(v0); h.y = __float2half(v1);
                    *(__half2*)(Ch + row * ldch + col) = h;
                }
            }
        }
}

// speaker-split relation fp16 GEMM
__global__ __launch_bounds__(256, 2) void hgemm_rel()
{
    const int M0 = g_meta[0], M0pad = g_meta[1], M1 = g_meta[2], M1pad = g_meta[3];
    const int m0 = blockIdx.y * 128;
    if (m0 >= M0pad + M1pad) return;
    const int grp = (m0 < M0pad) ? 0 : 1;
    const int n0 = blockIdx.x * 128, j = blockIdx.z;

    extern __shared__ __half smh[];
    __shared__ int sidx[128];
    const uint32_t asb = (uint32_t)__cvta_generic_to_shared(smh);
    const uint32_t bsb = (uint32_t)__cvta_generic_to_shared(smh + HNST * HSTG);

    const int tid = threadIdx.x, lane = tid & 31, wid = tid >> 5;
    const int wm = wid & 1, wn = wid >> 1, g = lane >> 2, t = lane & 3;

    if (tid < 128) sidx[tid] = g_idx[m0 + tid];

    const int ar = tid >> 1, ac = (tid & 1) * 16;
    const int bkr = tid >> 4, bnc = (tid & 15) * 8;
    const __half* Arow = g_xh + (long long)g_idx[m0 + ar] * DD;
    const __half* B = g_Wrelh + (long long)(grp * 4 + j) * DD * HH;

    float acc[4][4][4];
    #pragma unroll
    for (int i = 0; i < 4; i++)
        #pragma unroll
        for (int jj = 0; jj < 4; jj++)
            #pragma unroll
            for (int e = 0; e < 4; e++) acc[i][jj][e] = 0.f;

    auto fill = [&](int s, int k0) {
        const uint32_t ab = asb + (uint32_t)(s * HSTG * 2);
        cp16(ab + (ar * HAP + ac) * 2,     Arow + k0 + ac);
        cp16(ab + (ar * HAP + ac + 8) * 2, Arow + k0 + ac + 8);
        const uint32_t bb = bsb + (uint32_t)(s * HSTG * 2);
        cp16(bb + (bkr * HBPK + bnc) * 2,        B + (long long)(k0 + bkr) * HH + n0 + bnc);
        cp16(bb + ((bkr + 16) * HBPK + bnc) * 2, B + (long long)(k0 + bkr + 16) * HH + n0 + bnc);
    };

    fill(0, 0);   asm volatile("cp.async.commit_group;");
    fill(1, 32);  asm volatile("cp.async.commit_group;");
    fill(2, 64);  asm volatile("cp.async.commit_group;");
    fill(3, 96);  asm volatile("cp.async.commit_group;");

    const int KT = DD / 32;
    int s = 0, sp = 4;
    for (int kt = 0; kt < KT; kt++) {
        asm volatile("cp.async.wait_group 3;" ::: "memory");
        __syncthreads();
        if (kt + 4 < KT) fill(sp, (kt + 4) * 32);
        asm volatile("cp.async.commit_group;");
        slab_h<false>(asb + (uint32_t)((s * HSTG) * 2),
                      bsb + (uint32_t)((s * HSTG) * 2), wm, wn, lane, acc);
        if (++s == HNST) s = 0;
        if (++sp == HNST) sp = 0;
    }

    #pragma unroll
    for (int mt = 0; mt < 4; mt++)
        #pragma unroll
        for (int nt = 0; nt < 4; nt++) {
            const int col = j * HH + n0 + wn * 32 + nt * 8 + t * 2;
            #pragma unroll
            for (int half = 0; half < 2; half++) {
                const int lr = wm * 64 + mt * 16 + g + half * 8;
                const int pr = m0 + lr;
                const bool valid = (grp == 0) ? (pr < M0) : (pr - M0pad < M1);
                if (valid) {
                    __half2 h;
                    h.x = __float2half(acc[mt][nt][half * 2]);
                    h.y = __float2half(acc[mt][nt][half * 2 + 1]);
                    *(__half2*)(g_HA4h + (long long)sidx[lr] * HA4_COLS + col) = h;
                }
            }
        }
}

// ================= glue =================
__global__ void part_count(const int* __restrict__ sp)
{
    const int n = blockIdx.x * blockDim.x + threadIdx.x;
    if (n < MTILES * 128) g_idx[n] = 0;
    if (n < NTOT) atomicAdd(&g_cnt[sp[(n & 255) * BB + (n >> 8)]], 1);
}
__global__ void part_meta()
{
    const int M0 = g_cnt[0], M1 = g_cnt[1];
    g_meta[0] = M0; g_meta[1] = ((M0 + 127) / 128) * 128;
    g_meta[2] = M1; g_meta[3] = ((M1 + 127) / 128) * 128;
    g_cnt[0] = g_cnt[1] = g_cnt2[0] = g_cnt2[1] = 0;
}
__global__ void part_assign(const int* __restrict__ sp)
{
    const int n = blockIdx.x * blockDim.x + threadIdx.x;
    if (n >= NTOT) return;
    const int s = sp[(n & 255) * BB + (n >> 8)];
    const int slot = atomicAdd(&g_cnt2[s], 1);
    g_idx[(s == 0) ? slot : g_meta[1] + slot] = n;
}
__global__ void f2h_kernel(const float* __restrict__ s, __half* __restrict__ d, int n)
{
    int i = (blockIdx.x * blockDim.x + threadIdx.x) * 4;
    if (i + 3 < n) {
        float4 v = *(const float4*)(s + i);
        __half2 a, b;
        a.x = __float2half(v.x); a.y = __float2half(v.y);
        b.x = __float2half(v.z); b.y = __float2half(v.w);
        *(__half2*)(d + i) = a;
        *(__half2*)(d + i + 2) = b;
    }
}
__global__ void make_x_kernel(const float* __restrict__ f)
{
    const int n = blockIdx.x, b = n >> 8, s = n & 255;
    const float* src = f + ((long long)s * BB + b) * DD;
    for (int d = threadIdx.x; d < DD; d += blockDim.x) {
        const __half h = __float2half(src[d]);
        g_emh[(long long)n * DHE + d] = h;
        g_xh [(long long)n * DD  + d] = h;
    }
}
__global__ void build_wcat(const float* __restrict__ Wn, const float* __restrict__ Ws)
{
    const int i = blockIdx.x * blockDim.x + threadIdx.x;
    if (i < HH * HH) {
        g_Wcath[i] = __float2half(Wn[i]);
        g_Wcath[HH * HH + i] = __float2half(Ws[i]);
    }
}
__global__ void build_wpr(const float* __restrict__ Ws, const float* __restrict__ Wr,
                          const float* __restrict__ br)
{
    const int i = blockIdx.x * blockDim.x + threadIdx.x;
    if (i < DD * PRN) {
        const int d = i / PRN, c = i % PRN;
        g_Wprh[i] = __float2half((c < 256) ? Ws[d * 256 + c] : Wr[d * 512 + (c - 256)]);
    }
    if (i < PRN) g_bias768[i] = (i < 256) ? 0.f : br[i - 256];
}
__global__ __launch_bounds__(256) void edge_softmax_kernel()
{
    const int b = blockIdx.x;
    const int i = threadIdx.x;
    const float* Pb = g_PR + (long long)b * 256 * PRN;

    float m = -1e30f;
    for (int s = 0; s < LSEQ; s++)
        m = fmaxf(m, Pb[(long long)s * PRN + i]);

    float Z = 0.f;
    for (int s = 0; s < LSEQ; s++)
        Z += __expf(Pb[(long long)s * PRN + i] - m);

    float ew[WSZ];
    float Swin = 0.f;
    #pragma unroll
    for (int d = 0; d < WSZ; d++) {
        const int s = i - WINR + d;
        float e = 0.f;
        if (s >= 0 && s < LSEQ) {
            e = __expf(Pb[(long long)s * PRN + i] - m);
            Swin += e;
        }
        ew[d] = e;
    }
    const float den = Swin + 1e-10f * (Z - Swin);
    float* dst = g_EW + ((long long)(b * 256 + i)) * WSZ;
    #pragma unroll
    for (int d = 0; d < WSZ; d++)
        dst[d] = ew[d] / den;
}
__global__ __launch_bounds__(512) void rgcn_agg_kernel(const int* __restrict__ sp)
{
    const int n = blockIdx.x, b = n >> 8, k = n & 255, h = threadIdx.x;
    __shared__ float w[WSZ];
    const int lo = max(k - WINR, 0), hi = min(k + WINR, LSEQ - 1);
    const int cnt = hi - lo + 1;
    if (h < cnt) {
        const int i = lo + h;
        w[h] = g_EW[((long long)(b * 256 + i)) * WSZ + (k - i + WINR)];
    }
    __syncthreads();
    const int spk = sp[k * BB + b];
    float acc = g_PR[(long long)n * PRN + 256 + h];
    for (int t = 0; t < cnt; t++) {
        const int i = lo + t;
        const int j = spk * 2 + ((i < k) ? 0 : 1);
        acc += w[t] * __half2float(g_HA4h[((long long)(b * 256 + i)) * HA4_COLS + j * HH + h]);
    }
    g_cat [(long long)n * HH + h] = acc;
    g_cath[(long long)n * CATK + HH + h] = __float2half(acc);
}
__global__ __launch_bounds__(512) void nbr_kernel()
{
    const int b = blockIdx.x, ks = blockIdx.y * 64, h = threadIdx.x;
    float run = 0.f;
    const int lo = max(ks - WINR, 0), hi = min(ks + WINR, LSEQ - 1);
    for (int j = lo; j <= hi; j++) run += g_cat[((long long)(b * 256 + j)) * HH + h];
    g_cath[((long long)(b * 256 + ks)) * CATK + h] = __float2half(run);
    for (int k = ks + 1; k < ks + 64; k++) {
        if (k + WINR < LSEQ) run += g_cat[((long long)(b * 256 + k + WINR)) * HH + h];
        if (k - WINR - 1 >= 0) run -= g_cat[((long long)(b * 256 + k - WINR - 1)) * HH + h];
        g_cath[((long long)(b * 256 + k)) * CATK + h] = __float2half(run);
    }
}
__global__ void softmax_rows_kernel()
{
    __shared__ float red[256];
    const long long r = blockIdx.x;
    const int s = threadIdx.x;
    const float v = g_S[r * 256 + s];
    red[s] = v; __syncthreads();
    for (int o = 128; o > 0; o >>= 1) { if (s < o) red[s] = fmaxf(red[s], red[s + o]); __syncthreads(); }
    const float m = red[0]; __syncthreads();
    const float e = __expf(v - m);
    red[s] = e; __syncthreads();
    for (int o = 128; o > 0; o >>= 1) { if (s < o) red[s] += red[s + o]; __syncthreads(); }
    g_Sh[r * 256 + s] = __float2half(e / red[0]);
}
__global__ void final_kernel(const float* __restrict__ W_fc,
                             const float* __restrict__ b_fc, float* __restrict__ out)
{
    const int gw = (blockIdx.x * blockDim.x + threadIdx.x) >> 5;
    const int lane = threadIdx.x & 31;
    if (gw >= NTOT) return;
    float p[CC] = {0.f, 0.f, 0.f, 0.f, 0.f, 0.f};
    #pragma unroll
    for (int j = 0; j < 16; j++) {
        const int hx = lane + j * 32;
        const float hv = g_HID[(long long)gw * HH + hx];
        const float* wr = W_fc + (long long)hx * CC;
        #pragma unroll
        for (int c = 0; c < CC; c++) p[c] += hv * wr[c];
    }
    #pragma unroll
    for (int o = 16; o > 0; o >>= 1)
        #pragma unroll
        for (int c = 0; c < CC; c++) p[c] += __shfl_down_sync(0xffffffffu, p[c], o);
    if (lane == 0) {
        float lg[CC], m = -1e30f;
        #pragma unroll
        for (int c = 0; c < CC; c++) { lg[c] = p[c] + b_fc[c]; m = fmaxf(m, lg[c]); }
        float ss = 0.f;
        #pragma unroll
        for (int c = 0; c < CC; c++) ss += __expf(lg[c] - m);
        const float lse = m + logf(ss);
        #pragma unroll
        for (int c = 0; c < CC; c++) out[(long long)gw * CC + c] = lg[c] - lse;
    }
}

// ================= host =================
extern "C" void kernel_launch(void* const* d_in, const int* in_sizes, int n_in,
                              void* d_out, int out_size)
{
    const float* features = (const float*)d_in[0];
    const float* Wscalar  = (const float*)d_in[1];
    const float* W_rel    = (const float*)d_in[2];
    const float* W_root   = (const float*)d_in[3];
    const float* b_rgcn   = (const float*)d_in[4];
    const float* W_nbr    = (const float*)d_in[5];
    const float* W_self   = (const float*)d_in[6];
    const float* b_gc     = (const float*)d_in[7];
    const float* W_match  = (const float*)d_in[8];
    const float* b_match  = (const float*)d_in[9];
    const float* W_lin    = (const float*)d_in[10];
    const float* b_lin    = (const float*)d_in[11];
    const float* W_fc     = (const float*)d_in[12];
    const float* b_fc     = (const float*)d_in[13];
    const int*   speakers = (const int*)  d_in[14];
    float* out = (float*)d_out;

    float *PR, *S, *HID, *b768;
    __half *xh, *emh, *cath, *XTh, *Sh, *ATTh, *Wprh, *Wrelh, *Wcath, *Wmh, *Wlinh;
    cudaGetSymbolAddress((void**)&PR,  g_PR);
    cudaGetSymbolAddress((void**)&S,   g_S);
    cudaGetSymbolAddress((void**)&HID, g_HID);
    cudaGetSymbolAddress((void**)&b768,g_bias768);
    cudaGetSymbolAddress((void**)&xh,  g_xh);
    cudaGetSymbolAddress((void**)&emh, g_emh);
    cudaGetSymbolAddress((void**)&cath,g_cath);
    cudaGetSymbolAddress((void**)&XTh, g_XTh);
    cudaGetSymbolAddress((void**)&Sh,  g_Sh);
    cudaGetSymbolAddress((void**)&ATTh,g_ATTh);
    cudaGetSymbolAddress((void**)&Wprh, g_Wprh);
    cudaGetSymbolAddress((void**)&Wrelh,g_Wrelh);
    cudaGetSymbolAddress((void**)&Wcath,g_Wcath);
    cudaGetSymbolAddress((void**)&Wmh,  g_Wmh);
    cudaGetSymbolAddress((void**)&Wlinh,g_Wlinh);

    cudaFuncSetAttribute(hgemm<0,false,true,true,false>, cudaFuncAttributeMaxDynamicSharedMemorySize, HSMEM);
    cudaFuncSetAttribute(hgemm<0,false,true,false,true>, cudaFuncAttributeMaxDynamicSharedMemorySize, HSMEM);
    cudaFuncSetAttribute(hgemm<2,true,false,true,false>, cudaFuncAttributeMaxDynamicSharedMemorySize, HSMEM);
    cudaFuncSetAttribute(hgemm<0,false,false,false,true>,cudaFuncAttributeMaxDynamicSharedMemorySize, HSMEM);
    cudaFuncSetAttribute(hgemm<1,false,true,true,false>, cudaFuncAttributeMaxDynamicSharedMemorySize, HSMEM);
    cudaFuncSetAttribute(hgemm_rel,                      cudaFuncAttributeMaxDynamicSharedMemorySize, HSMEM);

    cudaStream_t s2;
    cudaStreamCreateWithFlags(&s2, cudaStreamNonBlocking);
    cudaEvent_t e1, e2;
    cudaEventCreateWithFlags(&e1, cudaEventDisableTiming);
    cudaEventCreateWithFlags(&e2, cudaEventDisableTiming);

    // --- s2: independent weight conversions start immediately ---
    f2h_kernel<<<(8*DD*HH/4 + 255)/256, 256, 0, s2>>>(W_rel, Wrelh, 8*DD*HH);
    f2h_kernel<<<(DHE*DHE/4 + 255)/256, 256, 0, s2>>>(W_match, Wmh, DHE*DHE);
    f2h_kernel<<<(DHE*HH/4 + 255)/256, 256, 0, s2>>>(W_lin, Wlinh, DHE*HH);

    // --- stream 0: activation transpose, fused weights, partition ---
    make_x_kernel<<<NTOT, 256>>>(features);
    build_wcat<<<(HH*HH + 255)/256, 256>>>(W_nbr, W_self);
    build_wpr<<<(DD*PRN + 255)/256, 256>>>(Wscalar, W_root, b_rgcn);
    part_count<<<(MTILES*128 + 255)/256, 256>>>(speakers);
    part_meta<<<1, 1>>>();
    part_assign<<<(NTOT + 255)/256, 256>>>(speakers);

    // fork: rel GEMM on s2 (after its Wrelh conversion, and after e1 deps)
    cudaEventRecord(e1, 0);
    cudaStreamWaitEvent(s2, e1, 0);
    hgemm_rel<<<dim3(HH/128, MTILES, 4), 256, HSMEM, s2>>>();
    cudaEventRecord(e2, s2);

    // 1. [P | root] = xh @ Wprh + [0|b_rgcn]
    hgemm<0,false,true,true,false><<<dim3(PRN/128, NTOT/128), 256, HSMEM>>>(
        xh, Wprh, PR, nullptr, b768, DD, DD, PRN, PRN, 0, 0, 0, 0);

    // 2. edge softmax
    edge_softmax_kernel<<<BB, 256>>>();

    cudaStreamWaitEvent(0, e2, 0);

    // 3. RGCN aggregation; neighbor window
    rgcn_agg_kernel<<<NTOT, 512>>>(speakers);
    nbr_kernel<<<dim3(BB, LSEQ/64), 512>>>();

    // 4. h2 = cath @ Wcath + b_gc -> emh upper
    hgemm<0,false,true,false,true><<<dim3(HH/128, NTOT/128), 256, HSMEM>>>(
        cath, Wcath, nullptr, emh + DD, b_gc, CATK, CATK, HH, 0, DHE, 0, 0, 0);

    // 5. XTh = emh @ Wmh + b_match
    hgemm<0,false,true,false,true><<<dim3(DHE/128, NTOT/128), 256, HSMEM>>>(
        emh, Wmh, nullptr, XTh, b_match, DHE, DHE, DHE, 0, DHE, 0, 0, 0);

    // 6. S = tanh(XTh @ emh^T) batched; softmax
    hgemm<2,true,false,true,false><<<dim3(LSEQ/128, LSEQ/128, BB), 256, HSMEM>>>(
        XTh, emh, S, nullptr, nullptr, DHE, DHE, DHE, LSEQ, 0,
        (long long)LSEQ*DHE, (long long)LSEQ*DHE, (long long)LSEQ*LSEQ);
    softmax_rows_kernel<<<BB*LSEQ, 256>>>();

    // 7. ATTh = Sh @ emh
    hgemm<0,false,false,false,true><<<dim3(DHE/128, LSEQ/128, BB), 256, HSMEM>>>(
        Sh, emh, nullptr, ATTh, nullptr, LSEQ, LSEQ, DHE, 0, DHE,
        (long long)LSEQ*LSEQ, (long long)LSEQ*DHE, (long long)LSEQ*DHE);

    // 8. HID = relu(ATTh @ Wlinh + b_lin)
    hgemm<1,false,true,true,false><<<dim3(HH/128, NTOT/128), 256, HSMEM>>>(
        ATTh, Wlinh, HID, nullptr, b_lin, DHE, DHE, HH, HH, 0, 0, 0, 0);

    // 9. output
    final_kernel<<<(NTOT*32 + 127)/128, 128>>>(W_fc, b_fc, out);
}

// round 15
// speedup vs baseline: 1.2429x; 1.0334x over previous
#include <cuda_runtime.h>
#include <cuda_fp16.h>
#include <math.h>
#include <stdint.h>

#define LSEQ 256
#define BB   64
#define DD   1024
#define HH   512
#define CC   6
#define NTOT 16384
#define DHE  1536
#define WINR 10
#define WSZ  21
#define HA4_COLS 2048
#define MTILES 129
#define CATK 1024
#define PRN  768

// ---------------- scratch ----------------
__device__ __align__(256) float g_PR  [(size_t)NTOT * PRN];
__device__ __align__(256) float g_EW  [(size_t)BB * LSEQ * WSZ];
__device__ __align__(256) float g_cat [(size_t)NTOT * HH];
__device__ __align__(256) float g_S   [(size_t)BB * LSEQ * LSEQ];
__device__ __align__(256) float g_HID [(size_t)NTOT * HH];
__device__ __align__(256) float g_bias768[PRN];
// fp16
__device__ __align__(256) __half g_xh  [(size_t)NTOT * DD];
__device__ __align__(256) __half g_HA4h[(size_t)NTOT * HA4_COLS];
__device__ __align__(256) __half g_cath[(size_t)NTOT * CATK];
__device__ __align__(256) __half g_emh [(size_t)NTOT * DHE];
__device__ __align__(256) __half g_XTh [(size_t)NTOT * DHE];
__device__ __align__(256) __half g_Sh  [(size_t)BB * LSEQ * LSEQ];
__device__ __align__(256) __half g_EmWh[(size_t)NTOT * HH];   // em @ W_lin + b_lin
__device__ __align__(256) __half g_Wprh [(size_t)DD * PRN];
__device__ __align__(256) __half g_Wrelh[(size_t)8 * DD * HH];
__device__ __align__(256) __half g_Wcath[(size_t)CATK * HH];
__device__ __align__(256) __half g_Wmh  [(size_t)DHE * DHE];
__device__ __align__(256) __half g_Wlinh[(size_t)DHE * HH];

__device__ int g_cnt[2], g_cnt2[2], g_meta[4], g_idx[MTILES * 128];

__device__ __forceinline__ void cp16(uint32_t d, const void* s) {
    asm volatile("cp.async.cg.shared.global [%0], [%1], 16;" :: "r"(d), "l"(s));
}
__device__ __forceinline__ void ldm4(uint32_t* r, uint32_t a) {
    asm volatile("ldmatrix.sync.aligned.m8n8.x4.shared.b16 {%0,%1,%2,%3}, [%4];"
                 : "=r"(r[0]), "=r"(r[1]), "=r"(r[2]), "=r"(r[3]) : "r"(a));
}
__device__ __forceinline__ void ldm4t(uint32_t* r, uint32_t a) {
    asm volatile("ldmatrix.sync.aligned.m8n8.x4.trans.shared.b16 {%0,%1,%2,%3}, [%4];"
                 : "=r"(r[0]), "=r"(r[1]), "=r"(r[2]), "=r"(r[3]) : "r"(a));
}
__device__ __forceinline__ void mma16816(float* c, const uint32_t* a, const uint32_t* b) {
    asm volatile("mma.sync.aligned.m16n8k16.row.col.f32.f16.f16.f32 "
        "{%0,%1,%2,%3}, {%4,%5,%6,%7}, {%8,%9}, {%0,%1,%2,%3};"
        : "+f"(c[0]), "+f"(c[1]), "+f"(c[2]), "+f"(c[3])
        : "r"(a[0]), "r"(a[1]), "r"(a[2]), "r"(a[3]), "r"(b[0]), "r"(b[1]));
}

// ================= fp16 hgemm: 128x128 tile, BK=32, 5-stage =================
#define HAP  40
#define HBPK 136
#define HSTG 5120
#define HNST 5
#define HSMEM (2 * HNST * HSTG * 2)   // 102400

template<bool BT>
__device__ __forceinline__ void slab_h(uint32_t ab, uint32_t bb, int wm, int wn,
                                       int lane, float acc[4][4][4])
{
    const int lr = lane & 15;
    const int lc = (lane >> 4) << 3;
    #pragma unroll
    for (int ks = 0; ks < 32; ks += 16) {
        uint32_t af[4][4], bf[4][2];
        #pragma unroll
        for (int mt = 0; mt < 4; mt++)
            ldm4(af[mt], ab + (uint32_t)(((wm * 64 + mt * 16 + lr) * HAP + ks + lc) * 2));
        #pragma unroll
        for (int np = 0; np < 2; np++) {
            uint32_t r[4];
            if (!BT)
                ldm4t(r, bb + (uint32_t)(((ks + lr) * HBPK + wn * 32 + np * 16 + lc) * 2));
            else
                ldm4(r, bb + (uint32_t)(((wn * 32 + np * 16 + (lane >> 4) * 8 + (lane & 7)) * HAP
                                          + ks + (lane & 8)) * 2));
            bf[2*np][0]   = r[0]; bf[2*np][1]   = r[1];
            bf[2*np+1][0] = r[2]; bf[2*np+1][1] = r[3];
        }
        #pragma unroll
        for (int mt = 0; mt < 4; mt++)
            #pragma unroll
            for (int nt = 0; nt < 4; nt++)
                mma16816(acc[mt][nt], af[mt], bf[nt]);
    }
}

template<int ACT, bool BT, bool BIAS, bool WF, bool WH>
__global__ __launch_bounds__(256, 2) void hgemm(
    const __half* __restrict__ A, const __half* __restrict__ B,
    float* __restrict__ Cf, __half* __restrict__ Ch, const float* __restrict__ bias,
    int K, int lda, int ldb, int ldcf, int ldch,
    long long zA, long long zB, long long zC)
{
    A += (long long)blockIdx.z * zA;
    B += (long long)blockIdx.z * zB;
    if (WF) Cf += (long long)blockIdx.z * zC;
    if (WH) Ch += (long long)blockIdx.z * zC;

    extern __shared__ __half smh[];
    const uint32_t asb = (uint32_t)__cvta_generic_to_shared(smh);
    const uint32_t bsb = (uint32_t)__cvta_generic_to_shared(smh + HNST * HSTG);

    const int tid = threadIdx.x, lane = tid & 31, wid = tid >> 5;
    const int wm = wid & 1, wn = wid >> 1, g = lane >> 2, t = lane & 3;
    const int m0 = blockIdx.y * 128, n0 = blockIdx.x * 128;

    const int ar = tid >> 1, ac = (tid & 1) * 16;
    const int bkr = tid >> 4, bnc = (tid & 15) * 8;

    float acc[4][4][4];
    #pragma unroll
    for (int i = 0; i < 4; i++)
        #pragma unroll
        for (int j = 0; j < 4; j++)
            #pragma unroll
            for (int e = 0; e < 4; e++) acc[i][j][e] = 0.f;

    const int KT = K / 32;
    auto fill = [&](int s, int k0) {
        const uint32_t ab = asb + (uint32_t)(s * HSTG * 2);
        cp16(ab + (ar * HAP + ac) * 2,     A + (long long)(m0 + ar) * lda + k0 + ac);
        cp16(ab + (ar * HAP + ac + 8) * 2, A + (long long)(m0 + ar) * lda + k0 + ac + 8);
        const uint32_t bb = bsb + (uint32_t)(s * HSTG * 2);
        if (!BT) {
            cp16(bb + (bkr * HBPK + bnc) * 2,        B + (long long)(k0 + bkr) * ldb + n0 + bnc);
            cp16(bb + ((bkr + 16) * HBPK + bnc) * 2, B + (long long)(k0 + bkr + 16) * ldb + n0 + bnc);
        } else {
            cp16(bb + (ar * HAP + ac) * 2,     B + (long long)(n0 + ar) * ldb + k0 + ac);
            cp16(bb + (ar * HAP + ac + 8) * 2, B + (long long)(n0 + ar) * ldb + k0 + ac + 8);
        }
    };

    fill(0, 0);   asm volatile("cp.async.commit_group;");
    fill(1, 32);  asm volatile("cp.async.commit_group;");
    fill(2, 64);  asm volatile("cp.async.commit_group;");
    fill(3, 96);  asm volatile("cp.async.commit_group;");

    int s = 0, sp = 4;
    for (int kt = 0; kt < KT; kt++) {
        asm volatile("cp.async.wait_group 3;" ::: "memory");
        __syncthreads();
        if (kt + 4 < KT) fill(sp, (kt + 4) * 32);
        asm volatile("cp.async.commit_group;");
        slab_h<BT>(asb + (uint32_t)((s * HSTG) * 2),
                   bsb + (uint32_t)((s * HSTG) * 2), wm, wn, lane, acc);
        if (++s == HNST) s = 0;
        if (++sp == HNST) sp = 0;
    }

    #pragma unroll
    for (int mt = 0; mt < 4; mt++)
        #pragma unroll
        for (int nt = 0; nt < 4; nt++) {
            const int col = n0 + wn * 32 + nt * 8 + t * 2;
            #pragma unroll
            for (int half = 0; half < 2; half++) {
                const long long row = m0 + wm * 64 + mt * 16 + g + half * 8;
                float v0 = acc[mt][nt][half * 2 + 0];
                float v1 = acc[mt][nt][half * 2 + 1];
                if (BIAS) { v0 += bias[col]; v1 += bias[col + 1]; }
                if (ACT == 1) { v0 = fmaxf(v0, 0.f); v1 = fmaxf(v1, 0.f); }
                if (ACT == 2) { v0 = tanhf(v0); v1 = tanhf(v1); }
                if (WF) *(float2*)(Cf + row * ldcf + col) = make_float2(v0, v1);
                if (WH) {
                    __half2 h; h.x = __float2half(v0); h.y = __float2half(v1);
                    *(__half2*)(Ch + row * ldch + col) = h;
                }
            }
        }
}

// speaker-split relation fp16 GEMM
__global__ __launch_bounds__(256, 2) void hgemm_rel()
{
    const int M0 = g_meta[0], M0pad = g_meta[1], M1 = g_meta[2], M1pad = g_meta[3];
    const int m0 = blockIdx.y * 128;
    if (m0 >= M0pad + M1pad) return;
    const int grp = (m0 < M0pad) ? 0 : 1;
    const int n0 = blockIdx.x * 128, j = blockIdx.z;

    extern __shared__ __half smh[];
    __shared__ int sidx[128];
    const uint32_t asb = (uint32_t)__cvta_generic_to_shared(smh);
    const uint32_t bsb = (uint32_t)__cvta_generic_to_shared(smh + HNST * HSTG);

    const int tid = threadIdx.x, lane = tid & 31, wid = tid >> 5;
    const int wm = wid & 1, wn = wid >> 1, g = lane >> 2, t = lane & 3;

    if (tid < 128) sidx[tid] = g_idx[m0 + tid];

    const int ar = tid >> 1, ac = (tid & 1) * 16;
    const int bkr = tid >> 4, bnc = (tid & 15) * 8;
    const __half* Arow = g_xh + (long long)g_idx[m0 + ar] * DD;
    const __half* B = g_Wrelh + (long long)(grp * 4 + j) * DD * HH;

    float acc[4][4][4];
    #pragma unroll
    for (int i = 0; i < 4; i++)
        #pragma unroll
        for (int jj = 0; jj < 4; jj++)
            #pragma unroll
            for (int e = 0; e < 4; e++) acc[i][jj][e] = 0.f;

    auto fill = [&](int s, int k0) {
        const uint32_t ab = asb + (uint32_t)(s * HSTG * 2);
        cp16(ab + (ar * HAP + ac) * 2,     Arow + k0 + ac);
        cp16(ab + (ar * HAP + ac + 8) * 2, Arow + k0 + ac + 8);
        const uint32_t bb = bsb + (uint32_t)(s * HSTG * 2);
        cp16(bb + (bkr * HBPK + bnc) * 2,        B + (long long)(k0 + bkr) * HH + n0 + bnc);
        cp16(bb + ((bkr + 16) * HBPK + bnc) * 2, B + (long long)(k0 + bkr + 16) * HH + n0 + bnc);
    };

    fill(0, 0);   asm volatile("cp.async.commit_group;");
    fill(1, 32);  asm volatile("cp.async.commit_group;");
    fill(2, 64);  asm volatile("cp.async.commit_group;");
    fill(3, 96);  asm volatile("cp.async.commit_group;");

    const int KT = DD / 32;
    int s = 0, sp = 4;
    for (int kt = 0; kt < KT; kt++) {
        asm volatile("cp.async.wait_group 3;" ::: "memory");
        __syncthreads();
        if (kt + 4 < KT) fill(sp, (kt + 4) * 32);
        asm volatile("cp.async.commit_group;");
        slab_h<false>(asb + (uint32_t)((s * HSTG) * 2),
                      bsb + (uint32_t)((s * HSTG) * 2), wm, wn, lane, acc);
        if (++s == HNST) s = 0;
        if (++sp == HNST) sp = 0;
    }

    #pragma unroll
    for (int mt = 0; mt < 4; mt++)
        #pragma unroll
        for (int nt = 0; nt < 4; nt++) {
            const int col = j * HH + n0 + wn * 32 + nt * 8 + t * 2;
            #pragma unroll
            for (int half = 0; half < 2; half++) {
                const int lr = wm * 64 + mt * 16 + g + half * 8;
                const int pr = m0 + lr;
                const bool valid = (grp == 0) ? (pr < M0) : (pr - M0pad < M1);
                if (valid) {
                    __half2 h;
                    h.x = __float2half(acc[mt][nt][half * 2]);
                    h.y = __float2half(acc[mt][nt][half * 2 + 1]);
                    *(__half2*)(g_HA4h + (long long)sidx[lr] * HA4_COLS + col) = h;
                }
            }
        }
}

// ================= glue =================
__global__ void part_count(const int* __restrict__ sp)
{
    const int n = blockIdx.x * blockDim.x + threadIdx.x;
    if (n < MTILES * 128) g_idx[n] = 0;
    if (n < NTOT) atomicAdd(&g_cnt[sp[(n & 255) * BB + (n >> 8)]], 1);
}
__global__ void part_meta()
{
    const int M0 = g_cnt[0], M1 = g_cnt[1];
    g_meta[0] = M0; g_meta[1] = ((M0 + 127) / 128) * 128;
    g_meta[2] = M1; g_meta[3] = ((M1 + 127) / 128) * 128;
    g_cnt[0] = g_cnt[1] = g_cnt2[0] = g_cnt2[1] = 0;
}
__global__ void part_assign(const int* __restrict__ sp)
{
    const int n = blockIdx.x * blockDim.x + threadIdx.x;
    if (n >= NTOT) return;
    const int s = sp[(n & 255) * BB + (n >> 8)];
    const int slot = atomicAdd(&g_cnt2[s], 1);
    g_idx[(s == 0) ? slot : g_meta[1] + slot] = n;
}
__global__ void f2h_kernel(const float* __restrict__ s, __half* __restrict__ d, int n)
{
    int i = (blockIdx.x * blockDim.x + threadIdx.x) * 4;
    if (i + 3 < n) {
        float4 v = *(const float4*)(s + i);
        __half2 a, b;
        a.x = __float2half(v.x); a.y = __float2half(v.y);
        b.x = __float2half(v.z); b.y = __float2half(v.w);
        *(__half2*)(d + i) = a;
        *(__half2*)(d + i + 2) = b;
    }
}
__global__ void make_x_kernel(const float* __restrict__ f)
{
    const int n = blockIdx.x, b = n >> 8, s = n & 255;
    const float* src = f + ((long long)s * BB + b) * DD;
    for (int d = threadIdx.x; d < DD; d += blockDim.x) {
        const __half h = __float2half(src[d]);
        g_emh[(long long)n * DHE + d] = h;
        g_xh [(long long)n * DD  + d] = h;
    }
}
__global__ void build_wcat(const float* __restrict__ Wn, const float* __restrict__ Ws)
{
    const int i = blockIdx.x * blockDim.x + threadIdx.x;
    if (i < HH * HH) {
        g_Wcath[i] = __float2half(Wn[i]);
        g_Wcath[HH * HH + i] = __float2half(Ws[i]);
    }
}
__global__ void build_wpr(const float* __restrict__ Ws, const float* __restrict__ Wr,
                          const float* __restrict__ br)
{
    const int i = blockIdx.x * blockDim.x + threadIdx.x;
    if (i < DD * PRN) {
        const int d = i / PRN, c = i % PRN;
        g_Wprh[i] = __float2half((c < 256) ? Ws[d * 256 + c] : Wr[d * 512 + (c - 256)]);
    }
    if (i < PRN) g_bias768[i] = (i < 256) ? 0.f : br[i - 256];
}
__global__ __launch_bounds__(256) void edge_softmax_kernel()
{
    const int b = blockIdx.x;
    const int i = threadIdx.x;
    const float* Pb = g_PR + (long long)b * 256 * PRN;

    float m = -1e30f;
    for (int s = 0; s < LSEQ; s++)
        m = fmaxf(m, Pb[(long long)s * PRN + i]);

    float Z = 0.f;
    for (int s = 0; s < LSEQ; s++)
        Z += __expf(Pb[(long long)s * PRN + i] - m);

    float ew[WSZ];
    float Swin = 0.f;
    #pragma unroll
    for (int d = 0; d < WSZ; d++) {
        const int s = i - WINR + d;
        float e = 0.f;
        if (s >= 0 && s < LSEQ) {
            e = __expf(Pb[(long long)s * PRN + i] - m);
            Swin += e;
        }
        ew[d] = e;
    }
    const float den = Swin + 1e-10f * (Z - Swin);
    float* dst = g_EW + ((long long)(b * 256 + i)) * WSZ;
    #pragma unroll
    for (int d = 0; d < WSZ; d++)
        dst[d] = ew[d] / den;
}
__global__ __launch_bounds__(512) void rgcn_agg_kernel(const int* __restrict__ sp)
{
    const int n = blockIdx.x, b = n >> 8, k = n & 255, h = threadIdx.x;
    __shared__ float w[WSZ];
    const int lo = max(k - WINR, 0), hi = min(k + WINR, LSEQ - 1);
    const int cnt = hi - lo + 1;
    if (h < cnt) {
        const int i = lo + h;
        w[h] = g_EW[((long long)(b * 256 + i)) * WSZ + (k - i + WINR)];
    }
    __syncthreads();
    const int spk = sp[k * BB + b];
    float acc = g_PR[(long long)n * PRN + 256 + h];
    for (int t = 0; t < cnt; t++) {
        const int i = lo + t;
        const int j = spk * 2 + ((i < k) ? 0 : 1);
        acc += w[t] * __half2float(g_HA4h[((long long)(b * 256 + i)) * HA4_COLS + j * HH + h]);
    }
    g_cat [(long long)n * HH + h] = acc;
    g_cath[(long long)n * CATK + HH + h] = __float2half(acc);
}
__global__ __launch_bounds__(512) void nbr_kernel()
{
    const int b = blockIdx.x, ks = blockIdx.y * 64, h = threadIdx.x;
    float run = 0.f;
    const int lo = max(ks - WINR, 0), hi = min(ks + WINR, LSEQ - 1);
    for (int j = lo; j <= hi; j++) run += g_cat[((long long)(b * 256 + j)) * HH + h];
    g_cath[((long long)(b * 256 + ks)) * CATK + h] = __float2half(run);
    for (int k = ks + 1; k < ks + 64; k++) {
        if (k + WINR < LSEQ) run += g_cat[((long long)(b * 256 + k + WINR)) * HH + h];
        if (k - WINR - 1 >= 0) run -= g_cat[((long long)(b * 256 + k - WINR - 1)) * HH + h];
        g_cath[((long long)(b * 256 + k)) * CATK + h] = __float2half(run);
    }
}
__global__ void softmax_rows_kernel()
{
    __shared__ float red[256];
    const long long r = blockIdx.x;
    const int s = threadIdx.x;
    const float v = g_S[r * 256 + s];
    red[s] = v; __syncthreads();
    for (int o = 128; o > 0; o >>= 1) { if (s < o) red[s] = fmaxf(red[s], red[s + o]); __syncthreads(); }
    const float m = red[0]; __syncthreads();
    const float e = __expf(v - m);
    red[s] = e; __syncthreads();
    for (int o = 128; o > 0; o >>= 1) { if (s < o) red[s] += red[s + o]; __syncthreads(); }
    g_Sh[r * 256 + s] = __float2half(e / red[0]);
}
__global__ void final_kernel(const float* __restrict__ W_fc,
                             const float* __restrict__ b_fc, float* __restrict__ out)
{
    const int gw = (blockIdx.x * blockDim.x + threadIdx.x) >> 5;
    const int lane = threadIdx.x & 31;
    if (gw >= NTOT) return;
    float p[CC] = {0.f, 0.f, 0.f, 0.f, 0.f, 0.f};
    #pragma unroll
    for (int j = 0; j < 16; j++) {
        const int hx = lane + j * 32;
        const float hv = g_HID[(long long)gw * HH + hx];
        const float* wr = W_fc + (long long)hx * CC;
        #pragma unroll
        for (int c = 0; c < CC; c++) p[c] += hv * wr[c];
    }
    #pragma unroll
    for (int o = 16; o > 0; o >>= 1)
        #pragma unroll
        for (int c = 0; c < CC; c++) p[c] += __shfl_down_sync(0xffffffffu, p[c], o);
    if (lane == 0) {
        float lg[CC], m = -1e30f;
        #pragma unroll
        for (int c = 0; c < CC; c++) { lg[c] = p[c] + b_fc[c]; m = fmaxf(m, lg[c]); }
        float ss = 0.f;
        #pragma unroll
        for (int c = 0; c < CC; c++) ss += __expf(lg[c] - m);
        const float lse = m + logf(ss);
        #pragma unroll
        for (int c = 0; c < CC; c++) out[(long long)gw * CC + c] = lg[c] - lse;
    }
}

// ================= host =================
extern "C" void kernel_launch(void* const* d_in, const int* in_sizes, int n_in,
                              void* d_out, int out_size)
{
    const float* features = (const float*)d_in[0];
    const float* Wscalar  = (const float*)d_in[1];
    const float* W_rel    = (const float*)d_in[2];
    const float* W_root   = (const float*)d_in[3];
    const float* b_rgcn   = (const float*)d_in[4];
    const float* W_nbr    = (const float*)d_in[5];
    const float* W_self   = (const float*)d_in[6];
    const float* b_gc     = (const float*)d_in[7];
    const float* W_match  = (const float*)d_in[8];
    const float* b_match  = (const float*)d_in[9];
    const float* W_lin    = (const float*)d_in[10];
    const float* b_lin    = (const float*)d_in[11];
    const float* W_fc     = (const float*)d_in[12];
    const float* b_fc     = (const float*)d_in[13];
    const int*   speakers = (const int*)  d_in[14];
    float* out = (float*)d_out;

    float *PR, *S, *HID, *b768;
    __half *xh, *emh, *cath, *XTh, *Sh, *EmWh, *Wprh, *Wrelh, *Wcath, *Wmh, *Wlinh;
    cudaGetSymbolAddress((void**)&PR,  g_PR);
    cudaGetSymbolAddress((void**)&S,   g_S);
    cudaGetSymbolAddress((void**)&HID, g_HID);
    cudaGetSymbolAddress((void**)&b768,g_bias768);
    cudaGetSymbolAddress((void**)&xh,  g_xh);
    cudaGetSymbolAddress((void**)&emh, g_emh);
    cudaGetSymbolAddress((void**)&cath,g_cath);
    cudaGetSymbolAddress((void**)&XTh, g_XTh);
    cudaGetSymbolAddress((void**)&Sh,  g_Sh);
    cudaGetSymbolAddress((void**)&EmWh,g_EmWh);
    cudaGetSymbolAddress((void**)&Wprh, g_Wprh);
    cudaGetSymbolAddress((void**)&Wrelh,g_Wrelh);
    cudaGetSymbolAddress((void**)&Wcath,g_Wcath);
    cudaGetSymbolAddress((void**)&Wmh,  g_Wmh);
    cudaGetSymbolAddress((void**)&Wlinh,g_Wlinh);

    cudaFuncSetAttribute(hgemm<0,false,true,true,false>, cudaFuncAttributeMaxDynamicSharedMemorySize, HSMEM);
    cudaFuncSetAttribute(hgemm<0,false,true,false,true>, cudaFuncAttributeMaxDynamicSharedMemorySize, HSMEM);
    cudaFuncSetAttribute(hgemm<2,true,false,true,false>, cudaFuncAttributeMaxDynamicSharedMemorySize, HSMEM);
    cudaFuncSetAttribute(hgemm<1,false,false,true,false>,cudaFuncAttributeMaxDynamicSharedMemorySize, HSMEM);
    cudaFuncSetAttribute(hgemm_rel,                      cudaFuncAttributeMaxDynamicSharedMemorySize, HSMEM);

    cudaStream_t s2;
    cudaStreamCreateWithFlags(&s2, cudaStreamNonBlocking);
    cudaEvent_t e1, e2;
    cudaEventCreateWithFlags(&e1, cudaEventDisableTiming);
    cudaEventCreateWithFlags(&e2, cudaEventDisableTiming);

    // --- s2: independent weight conversions start immediately ---
    f2h_kernel<<<(8*DD*HH/4 + 255)/256, 256, 0, s2>>>(W_rel, Wrelh, 8*DD*HH);
    f2h_kernel<<<(DHE*DHE/4 + 255)/256, 256, 0, s2>>>(W_match, Wmh, DHE*DHE);
    f2h_kernel<<<(DHE*HH/4 + 255)/256, 256, 0, s2>>>(W_lin, Wlinh, DHE*HH);

    // --- stream 0: activation transpose, fused weights, partition ---
    make_x_kernel<<<NTOT, 256>>>(features);
    build_wcat<<<(HH*HH + 255)/256, 256>>>(W_nbr, W_self);
    build_wpr<<<(DD*PRN + 255)/256, 256>>>(Wscalar, W_root, b_rgcn);
    part_count<<<(MTILES*128 + 255)/256, 256>>>(speakers);
    part_meta<<<1, 1>>>();
    part_assign<<<(NTOT + 255)/256, 256>>>(speakers);

    // fork: rel GEMM on s2
    cudaEventRecord(e1, 0);
    cudaStreamWaitEvent(s2, e1, 0);
    hgemm_rel<<<dim3(HH/128, MTILES, 4), 256, HSMEM, s2>>>();
    cudaEventRecord(e2, s2);

    // 1. [P | root] = xh @ Wprh + [0|b_rgcn]
    hgemm<0,false,true,true,false><<<dim3(PRN/128, NTOT/128), 256, HSMEM>>>(
        xh, Wprh, PR, nullptr, b768, DD, DD, PRN, PRN, 0, 0, 0, 0);

    // 2. edge softmax
    edge_softmax_kernel<<<BB, 256>>>();

    cudaStreamWaitEvent(0, e2, 0);

    // 3. RGCN aggregation; neighbor window
    rgcn_agg_kernel<<<NTOT, 512>>>(speakers);
    nbr_kernel<<<dim3(BB, LSEQ/64), 512>>>();

    // 4. h2 = cath @ Wcath + b_gc -> emh upper
    hgemm<0,false,true,false,true><<<dim3(HH/128, NTOT/128), 256, HSMEM>>>(
        cath, Wcath, nullptr, emh + DD, b_gc, CATK, CATK, HH, 0, DHE, 0, 0, 0);

    // 5. EmWh = emh @ Wlinh + b_lin (fp16)  [re-associated attention output]
    hgemm<0,false,true,false,true><<<dim3(HH/128, NTOT/128), 256, HSMEM>>>(
        emh, Wlinh, nullptr, EmWh, b_lin, DHE, DHE, HH, 0, HH, 0, 0, 0);

    // 6. XTh = emh @ Wmh + b_match
    hgemm<0,false,true,false,true><<<dim3(DHE/128, NTOT/128), 256, HSMEM>>>(
        emh, Wmh, nullptr, XTh, b_match, DHE, DHE, DHE, 0, DHE, 0, 0, 0);

    // 7. S = tanh(XTh @ emh^T) batched; softmax
    hgemm<2,true,false,true,false><<<dim3(LSEQ/128, LSEQ/128, BB), 256, HSMEM>>>(
        XTh, emh, S, nullptr, nullptr, DHE, DHE, DHE, LSEQ, 0,
        (long long)LSEQ*DHE, (long long)LSEQ*DHE, (long long)LSEQ*LSEQ);
    softmax_rows_kernel<<<BB*LSEQ, 256>>>();

    // 8. HID = relu(Sh @ EmWh) batched (K=256)
    hgemm<1,false,false,true,false><<<dim3(HH/128, LSEQ/128, BB), 256, HSMEM>>>(
        Sh, EmWh, HID, nullptr, nullptr, LSEQ, LSEQ, HH, HH, 0,
        (long long)LSEQ*LSEQ, (long long)LSEQ*HH, (long long)LSEQ*HH);

    // 9. output
    final_kernel<<<(NTOT*32 + 127)/128, 128>>>(W_fc, b_fc, out);
}

// round 16
// speedup vs baseline: 1.2771x; 1.0275x over previous
#include <cuda_runtime.h>
#include <cuda_fp16.h>
#include <math.h>
#include <stdint.h>

#define LSEQ 256
#define BB   64
#define DD   1024
#define HH   512
#define CC   6
#define NTOT 16384
#define DHE  1536
#define WINR 10
#define WSZ  21
#define HA4_COLS 2048
#define MTILES 129
#define CATK 1024
#define PRN  768

// ---------------- scratch ----------------
__device__ __align__(256) float g_PR  [(size_t)NTOT * PRN];
__device__ __align__(256) float g_EW  [(size_t)BB * LSEQ * WSZ];
__device__ __align__(256) float g_cat [(size_t)NTOT * HH];
__device__ __align__(256) float g_S   [(size_t)BB * LSEQ * LSEQ];
__device__ __align__(256) float g_HID [(size_t)NTOT * HH];
__device__ __align__(256) float g_bias768[PRN];
// fp16
__device__ __align__(256) __half g_HA4h[(size_t)NTOT * HA4_COLS];
__device__ __align__(256) __half g_cath[(size_t)NTOT * CATK];
__device__ __align__(256) __half g_emh [(size_t)NTOT * DHE];
__device__ __align__(256) __half g_XTh [(size_t)NTOT * DHE];
__device__ __align__(256) __half g_Sh  [(size_t)BB * LSEQ * LSEQ];
__device__ __align__(256) __half g_EmWh[(size_t)NTOT * HH];
__device__ __align__(256) __half g_Wprh [(size_t)DD * PRN];
__device__ __align__(256) __half g_Wrelh[(size_t)8 * DD * HH];
__device__ __align__(256) __half g_Wcath[(size_t)CATK * HH];
__device__ __align__(256) __half g_Wmh  [(size_t)DHE * DHE];
__device__ __align__(256) __half g_Wlinh[(size_t)DHE * HH];

__device__ int g_cnt[2], g_cnt2[2], g_meta[4], g_idx[MTILES * 128];

__device__ __forceinline__ void cp16(uint32_t d, const void* s) {
    asm volatile("cp.async.cg.shared.global [%0], [%1], 16;" :: "r"(d), "l"(s));
}
__device__ __forceinline__ void ldm4(uint32_t* r, uint32_t a) {
    asm volatile("ldmatrix.sync.aligned.m8n8.x4.shared.b16 {%0,%1,%2,%3}, [%4];"
                 : "=r"(r[0]), "=r"(r[1]), "=r"(r[2]), "=r"(r[3]) : "r"(a));
}
__device__ __forceinline__ void ldm4t(uint32_t* r, uint32_t a) {
    asm volatile("ldmatrix.sync.aligned.m8n8.x4.trans.shared.b16 {%0,%1,%2,%3}, [%4];"
                 : "=r"(r[0]), "=r"(r[1]), "=r"(r[2]), "=r"(r[3]) : "r"(a));
}
__device__ __forceinline__ void mma16816(float* c, const uint32_t* a, const uint32_t* b) {
    asm volatile("mma.sync.aligned.m16n8k16.row.col.f32.f16.f16.f32 "
        "{%0,%1,%2,%3}, {%4,%5,%6,%7}, {%8,%9}, {%0,%1,%2,%3};"
        : "+f"(c[0]), "+f"(c[1]), "+f"(c[2]), "+f"(c[3])
        : "r"(a[0]), "r"(a[1]), "r"(a[2]), "r"(a[3]), "r"(b[0]), "r"(b[1]));
}

// ================= fp16 hgemm: 128x128 tile, BK=32, 5-stage =================
#define HAP  40
#define HBPK 136
#define HSTG 5120
#define HNST 5
#define HSMEM (2 * HNST * HSTG * 2)   // 102400

template<bool BT>
__device__ __forceinline__ void slab_h(uint32_t ab, uint32_t bb, int wm, int wn,
                                       int lane, float acc[4][4][4])
{
    const int lr = lane & 15;
    const int lc = (lane >> 4) << 3;
    #pragma unroll
    for (int ks = 0; ks < 32; ks += 16) {
        uint32_t af[4][4], bf[4][2];
        #pragma unroll
        for (int mt = 0; mt < 4; mt++)
            ldm4(af[mt], ab + (uint32_t)(((wm * 64 + mt * 16 + lr) * HAP + ks + lc) * 2));
        #pragma unroll
        for (int np = 0; np < 2; np++) {
            uint32_t r[4];
            if (!BT)
                ldm4t(r, bb + (uint32_t)(((ks + lr) * HBPK + wn * 32 + np * 16 + lc) * 2));
            else
                ldm4(r, bb + (uint32_t)(((wn * 32 + np * 16 + (lane >> 4) * 8 + (lane & 7)) * HAP
                                          + ks + (lane & 8)) * 2));
            bf[2*np][0]   = r[0]; bf[2*np][1]   = r[1];
            bf[2*np+1][0] = r[2]; bf[2*np+1][1] = r[3];
        }
        #pragma unroll
        for (int mt = 0; mt < 4; mt++)
            #pragma unroll
            for (int nt = 0; nt < 4; nt++)
                mma16816(acc[mt][nt], af[mt], bf[nt]);
    }
}

template<int ACT, bool BT, bool BIAS, bool WF, bool WH>
__global__ __launch_bounds__(256, 2) void hgemm(
    const __half* __restrict__ A, const __half* __restrict__ B,
    float* __restrict__ Cf, __half* __restrict__ Ch, const float* __restrict__ bias,
    int K, int lda, int ldb, int ldcf, int ldch,
    long long zA, long long zB, long long zC)
{
    A += (long long)blockIdx.z * zA;
    B += (long long)blockIdx.z * zB;
    if (WF) Cf += (long long)blockIdx.z * zC;
    if (WH) Ch += (long long)blockIdx.z * zC;

    extern __shared__ __half smh[];
    const uint32_t asb = (uint32_t)__cvta_generic_to_shared(smh);
    const uint32_t bsb = (uint32_t)__cvta_generic_to_shared(smh + HNST * HSTG);

    const int tid = threadIdx.x, lane = tid & 31, wid = tid >> 5;
    const int wm = wid & 1, wn = wid >> 1, g = lane >> 2, t = lane & 3;
    const int m0 = blockIdx.y * 128, n0 = blockIdx.x * 128;

    const int ar = tid >> 1, ac = (tid & 1) * 16;
    const int bkr = tid >> 4, bnc = (tid & 15) * 8;

    float acc[4][4][4];
    #pragma unroll
    for (int i = 0; i < 4; i++)
        #pragma unroll
        for (int j = 0; j < 4; j++)
            #pragma unroll
            for (int e = 0; e < 4; e++) acc[i][j][e] = 0.f;

    const int KT = K / 32;
    auto fill = [&](int s, int k0) {
        const uint32_t ab = asb + (uint32_t)(s * HSTG * 2);
        cp16(ab + (ar * HAP + ac) * 2,     A + (long long)(m0 + ar) * lda + k0 + ac);
        cp16(ab + (ar * HAP + ac + 8) * 2, A + (long long)(m0 + ar) * lda + k0 + ac + 8);
        const uint32_t bb = bsb + (uint32_t)(s * HSTG * 2);
        if (!BT) {
            cp16(bb + (bkr * HBPK + bnc) * 2,        B + (long long)(k0 + bkr) * ldb + n0 + bnc);
            cp16(bb + ((bkr + 16) * HBPK + bnc) * 2, B + (long long)(k0 + bkr + 16) * ldb + n0 + bnc);
        } else {
            cp16(bb + (ar * HAP + ac) * 2,     B + (long long)(n0 + ar) * ldb + k0 + ac);
            cp16(bb + (ar * HAP + ac + 8) * 2, B + (long long)(n0 + ar) * ldb + k0 + ac + 8);
        }
    };

    fill(0, 0);   asm volatile("cp.async.commit_group;");
    fill(1, 32);  asm volatile("cp.async.commit_group;");
    fill(2, 64);  asm volatile("cp.async.commit_group;");
    fill(3, 96);  asm volatile("cp.async.commit_group;");

    int s = 0, sp = 4;
    for (int kt = 0; kt < KT; kt++) {
        asm volatile("cp.async.wait_group 3;" ::: "memory");
        __syncthreads();
        if (kt + 4 < KT) fill(sp, (kt + 4) * 32);
        asm volatile("cp.async.commit_group;");
        slab_h<BT>(asb + (uint32_t)((s * HSTG) * 2),
                   bsb + (uint32_t)((s * HSTG) * 2), wm, wn, lane, acc);
        if (++s == HNST) s = 0;
        if (++sp == HNST) sp = 0;
    }

    #pragma unroll
    for (int mt = 0; mt < 4; mt++)
        #pragma unroll
        for (int nt = 0; nt < 4; nt++) {
            const int col = n0 + wn * 32 + nt * 8 + t * 2;
            #pragma unroll
            for (int half = 0; half < 2; half++) {
                const long long row = m0 + wm * 64 + mt * 16 + g + half * 8;
                float v0 = acc[mt][nt][half * 2 + 0];
                float v1 = acc[mt][nt][half * 2 + 1];
                if (BIAS) { v0 += bias[col]; v1 += bias[col + 1]; }
                if (ACT == 1) { v0 = fmaxf(v0, 0.f); v1 = fmaxf(v1, 0.f); }
                if (ACT == 2) { v0 = tanhf(v0); v1 = tanhf(v1); }
                if (WF) *(float2*)(Cf + row * ldcf + col) = make_float2(v0, v1);
                if (WH) {
                    __half2 h; h.x = __float2half(v0); h.y = __float2half(v1);
                    *(__half2*)(Ch + row * ldch + col) = h;
                }
            }
        }
}

// speaker-split relation fp16 GEMM (A rows gathered from g_emh[:, :1024])
__global__ __launch_bounds__(256, 2) void hgemm_rel()
{
    const int M0 = g_meta[0], M0pad = g_meta[1], M1 = g_meta[2], M1pad = g_meta[3];
    const int m0 = blockIdx.y * 128;
    if (m0 >= M0pad + M1pad) return;
    const int grp = (m0 < M0pad) ? 0 : 1;
    const int n0 = blockIdx.x * 128, j = blockIdx.z;

    extern __shared__ __half smh[];
    __shared__ int sidx[128];
    const uint32_t asb = (uint32_t)__cvta_generic_to_shared(smh);
    const uint32_t bsb = (uint32_t)__cvta_generic_to_shared(smh + HNST * HSTG);

    const int tid = threadIdx.x, lane = tid & 31, wid = tid >> 5;
    const int wm = wid & 1, wn = wid >> 1, g = lane >> 2, t = lane & 3;

    if (tid < 128) sidx[tid] = g_idx[m0 + tid];

    const int ar = tid >> 1, ac = (tid & 1) * 16;
    const int bkr = tid >> 4, bnc = (tid & 15) * 8;
    const __half* Arow = g_emh + (long long)g_idx[m0 + ar] * DHE;
    const __half* B = g_Wrelh + (long long)(grp * 4 + j) * DD * HH;

    float acc[4][4][4];
    #pragma unroll
    for (int i = 0; i < 4; i++)
        #pragma unroll
        for (int jj = 0; jj < 4; jj++)
            #pragma unroll
            for (int e = 0; e < 4; e++) acc[i][jj][e] = 0.f;

    auto fill = [&](int s, int k0) {
        const uint32_t ab = asb + (uint32_t)(s * HSTG * 2);
        cp16(ab + (ar * HAP + ac) * 2,     Arow + k0 + ac);
        cp16(ab + (ar * HAP + ac + 8) * 2, Arow + k0 + ac + 8);
        const uint32_t bb = bsb + (uint32_t)(s * HSTG * 2);
        cp16(bb + (bkr * HBPK + bnc) * 2,        B + (long long)(k0 + bkr) * HH + n0 + bnc);
        cp16(bb + ((bkr + 16) * HBPK + bnc) * 2, B + (long long)(k0 + bkr + 16) * HH + n0 + bnc);
    };

    fill(0, 0);   asm volatile("cp.async.commit_group;");
    fill(1, 32);  asm volatile("cp.async.commit_group;");
    fill(2, 64);  asm volatile("cp.async.commit_group;");
    fill(3, 96);  asm volatile("cp.async.commit_group;");

    const int KT = DD / 32;
    int s = 0, sp = 4;
    for (int kt = 0; kt < KT; kt++) {
        asm volatile("cp.async.wait_group 3;" ::: "memory");
        __syncthreads();
        if (kt + 4 < KT) fill(sp, (kt + 4) * 32);
        asm volatile("cp.async.commit_group;");
        slab_h<false>(asb + (uint32_t)((s * HSTG) * 2),
                      bsb + (uint32_t)((s * HSTG) * 2), wm, wn, lane, acc);
        if (++s == HNST) s = 0;
        if (++sp == HNST) sp = 0;
    }

    #pragma unroll
    for (int mt = 0; mt < 4; mt++)
        #pragma unroll
        for (int nt = 0; nt < 4; nt++) {
            const int col = j * HH + n0 + wn * 32 + nt * 8 + t * 2;
            #pragma unroll
            for (int half = 0; half < 2; half++) {
                const int lr = wm * 64 + mt * 16 + g + half * 8;
                const int pr = m0 + lr;
                const bool valid = (grp == 0) ? (pr < M0) : (pr - M0pad < M1);
                if (valid) {
                    __half2 h;
                    h.x = __float2half(acc[mt][nt][half * 2]);
                    h.y = __float2half(acc[mt][nt][half * 2 + 1]);
                    *(__half2*)(g_HA4h + (long long)sidx[lr] * HA4_COLS + col) = h;
                }
            }
        }
}

// ================= glue =================
__global__ void part_count(const int* __restrict__ sp)
{
    const int n = blockIdx.x * blockDim.x + threadIdx.x;
    if (n < MTILES * 128) g_idx[n] = 0;
    if (n < NTOT) atomicAdd(&g_cnt[sp[(n & 255) * BB + (n >> 8)]], 1);
}
__global__ void part_meta()
{
    const int M0 = g_cnt[0], M1 = g_cnt[1];
    g_meta[0] = M0; g_meta[1] = ((M0 + 127) / 128) * 128;
    g_meta[2] = M1; g_meta[3] = ((M1 + 127) / 128) * 128;
    g_cnt[0] = g_cnt[1] = g_cnt2[0] = g_cnt2[1] = 0;
}
__global__ void part_assign(const int* __restrict__ sp)
{
    const int n = blockIdx.x * blockDim.x + threadIdx.x;
    if (n >= NTOT) return;
    const int s = sp[(n & 255) * BB + (n >> 8)];
    const int slot = atomicAdd(&g_cnt2[s], 1);
    g_idx[(s == 0) ? slot : g_meta[1] + slot] = n;
}
__global__ void f2h_kernel(const float* __restrict__ s, __half* __restrict__ d, int n)
{
    int i = (blockIdx.x * blockDim.x + threadIdx.x) * 4;
    if (i + 3 < n) {
        float4 v = *(const float4*)(s + i);
        __half2 a, b;
        a.x = __float2half(v.x); a.y = __float2half(v.y);
        b.x = __float2half(v.z); b.y = __float2half(v.w);
        *(__half2*)(d + i) = a;
        *(__half2*)(d + i + 2) = b;
    }
}
__global__ void make_x_kernel(const float* __restrict__ f)
{
    const int n = blockIdx.x, b = n >> 8, s = n & 255;
    const float* src = f + ((long long)s * BB + b) * DD;
    for (int d = threadIdx.x; d < DD; d += blockDim.x)
        g_emh[(long long)n * DHE + d] = __float2half(src[d]);
}
__global__ void build_wcat(const float* __restrict__ Wn, const float* __restrict__ Ws)
{
    const int i = blockIdx.x * blockDim.x + threadIdx.x;
    if (i < HH * HH) {
        g_Wcath[i] = __float2half(Wn[i]);
        g_Wcath[HH * HH + i] = __float2half(Ws[i]);
    }
}
__global__ void build_wpr(const float* __restrict__ Ws, const float* __restrict__ Wr,
                          const float* __restrict__ br)
{
    const int i = blockIdx.x * blockDim.x + threadIdx.x;
    if (i < DD * PRN) {
        const int d = i / PRN, c = i % PRN;
        g_Wprh[i] = __float2half((c < 256) ? Ws[d * 256 + c] : Wr[d * 512 + (c - 256)]);
    }
    if (i < PRN) g_bias768[i] = (i < 256) ? 0.f : br[i - 256];
}
__global__ __launch_bounds__(256) void edge_softmax_kernel()
{
    const int b = blockIdx.x;
    const int i = threadIdx.x;
    const float* Pb = g_PR + (long long)b * 256 * PRN;

    float m = -1e30f;
    for (int s = 0; s < LSEQ; s++)
        m = fmaxf(m, Pb[(long long)s * PRN + i]);

    float Z = 0.f;
    for (int s = 0; s < LSEQ; s++)
        Z += __expf(Pb[(long long)s * PRN + i] - m);

    float ew[WSZ];
    float Swin = 0.f;
    #pragma unroll
    for (int d = 0; d < WSZ; d++) {
        const int s = i - WINR + d;
        float e = 0.f;
        if (s >= 0 && s < LSEQ) {
            e = __expf(Pb[(long long)s * PRN + i] - m);
            Swin += e;
        }
        ew[d] = e;
    }
    const float den = Swin + 1e-10f * (Z - Swin);
    float* dst = g_EW + ((long long)(b * 256 + i)) * WSZ;
    #pragma unroll
    for (int d = 0; d < WSZ; d++)
        dst[d] = ew[d] / den;
}
__global__ __launch_bounds__(512) void rgcn_agg_kernel(const int* __restrict__ sp)
{
    const int n = blockIdx.x, b = n >> 8, k = n & 255, h = threadIdx.x;
    __shared__ float w[WSZ];
    const int lo = max(k - WINR, 0), hi = min(k + WINR, LSEQ - 1);
    const int cnt = hi - lo + 1;
    if (h < cnt) {
        const int i = lo + h;
        w[h] = g_EW[((long long)(b * 256 + i)) * WSZ + (k - i + WINR)];
    }
    __syncthreads();
    const int spk = sp[k * BB + b];
    float acc = g_PR[(long long)n * PRN + 256 + h];
    for (int t = 0; t < cnt; t++) {
        const int i = lo + t;
        const int j = spk * 2 + ((i < k) ? 0 : 1);
        acc += w[t] * __half2float(g_HA4h[((long long)(b * 256 + i)) * HA4_COLS + j * HH + h]);
    }
    g_cat [(long long)n * HH + h] = acc;
    g_cath[(long long)n * CATK + HH + h] = __float2half(acc);
}
__global__ __launch_bounds__(512) void nbr_kernel()
{
    const int b = blockIdx.x, ks = blockIdx.y * 64, h = threadIdx.x;
    float run = 0.f;
    const int lo = max(ks - WINR, 0), hi = min(ks + WINR, LSEQ - 1);
    for (int j = lo; j <= hi; j++) run += g_cat[((long long)(b * 256 + j)) * HH + h];
    g_cath[((long long)(b * 256 + ks)) * CATK + h] = __float2half(run);
    for (int k = ks + 1; k < ks + 64; k++) {
        if (k + WINR < LSEQ) run += g_cat[((long long)(b * 256 + k + WINR)) * HH + h];
        if (k - WINR - 1 >= 0) run -= g_cat[((long long)(b * 256 + k - WINR - 1)) * HH + h];
        g_cath[((long long)(b * 256 + k)) * CATK + h] = __float2half(run);
    }
}
__global__ void softmax_rows_kernel()
{
    __shared__ float red[256];
    const long long r = blockIdx.x;
    const int s = threadIdx.x;
    const float v = g_S[r * 256 + s];
    red[s] = v; __syncthreads();
    for (int o = 128; o > 0; o >>= 1) { if (s < o) red[s] = fmaxf(red[s], red[s + o]); __syncthreads(); }
    const float m = red[0]; __syncthreads();
    const float e = __expf(v - m);
    red[s] = e; __syncthreads();
    for (int o = 128; o > 0; o >>= 1) { if (s < o) red[s] += red[s + o]; __syncthreads(); }
    g_Sh[r * 256 + s] = __float2half(e / red[0]);
}
__global__ void final_kernel(const float* __restrict__ W_fc,
                             const float* __restrict__ b_fc, float* __restrict__ out)
{
    const int gw = (blockIdx.x * blockDim.x + threadIdx.x) >> 5;
    const int lane = threadIdx.x & 31;
    if (gw >= NTOT) return;
    float p[CC] = {0.f, 0.f, 0.f, 0.f, 0.f, 0.f};
    #pragma unroll
    for (int j = 0; j < 16; j++) {
        const int hx = lane + j * 32;
        const float hv = g_HID[(long long)gw * HH + hx];
        const float* wr = W_fc + (long long)hx * CC;
        #pragma unroll
        for (int c = 0; c < CC; c++) p[c] += hv * wr[c];
    }
    #pragma unroll
    for (int o = 16; o > 0; o >>= 1)
        #pragma unroll
        for (int c = 0; c < CC; c++) p[c] += __shfl_down_sync(0xffffffffu, p[c], o);
    if (lane == 0) {
        float lg[CC], m = -1e30f;
        #pragma unroll
        for (int c = 0; c < CC; c++) { lg[c] = p[c] + b_fc[c]; m = fmaxf(m, lg[c]); }
        float ss = 0.f;
        #pragma unroll
        for (int c = 0; c < CC; c++) ss += __expf(lg[c] - m);
        const float lse = m + logf(ss);
        #pragma unroll
        for (int c = 0; c < CC; c++) out[(long long)gw * CC + c] = lg[c] - lse;
    }
}

// ================= host =================
extern "C" void kernel_launch(void* const* d_in, const int* in_sizes, int n_in,
                              void* d_out, int out_size)
{
    const float* features = (const float*)d_in[0];
    const float* Wscalar  = (const float*)d_in[1];
    const float* W_rel    = (const float*)d_in[2];
    const float* W_root   = (const float*)d_in[3];
    const float* b_rgcn   = (const float*)d_in[4];
    const float* W_nbr    = (const float*)d_in[5];
    const float* W_self   = (const float*)d_in[6];
    const float* b_gc     = (const float*)d_in[7];
    const float* W_match  = (const float*)d_in[8];
    const float* b_match  = (const float*)d_in[9];
    const float* W_lin    = (const float*)d_in[10];
    const float* b_lin    = (const float*)d_in[11];
    const float* W_fc     = (const float*)d_in[12];
    const float* b_fc     = (const float*)d_in[13];
    const int*   speakers = (const int*)  d_in[14];
    float* out = (float*)d_out;

    float *PR, *S, *HID, *b768;
    __half *emh, *cath, *XTh, *Sh, *EmWh, *Wprh, *Wrelh, *Wcath, *Wmh, *Wlinh;
    cudaGetSymbolAddress((void**)&PR,  g_PR);
    cudaGetSymbolAddress((void**)&S,   g_S);
    cudaGetSymbolAddress((void**)&HID, g_HID);
    cudaGetSymbolAddress((void**)&b768,g_bias768);
    cudaGetSymbolAddress((void**)&emh, g_emh);
    cudaGetSymbolAddress((void**)&cath,g_cath);
    cudaGetSymbolAddress((void**)&XTh, g_XTh);
    cudaGetSymbolAddress((void**)&Sh,  g_Sh);
    cudaGetSymbolAddress((void**)&EmWh,g_EmWh);
    cudaGetSymbolAddress((void**)&Wprh, g_Wprh);
    cudaGetSymbolAddress((void**)&Wrelh,g_Wrelh);
    cudaGetSymbolAddress((void**)&Wcath,g_Wcath);
    cudaGetSymbolAddress((void**)&Wmh,  g_Wmh);
    cudaGetSymbolAddress((void**)&Wlinh,g_Wlinh);

    cudaFuncSetAttribute(hgemm<0,false,true,true,false>, cudaFuncAttributeMaxDynamicSharedMemorySize, HSMEM);
    cudaFuncSetAttribute(hgemm<0,false,true,false,true>, cudaFuncAttributeMaxDynamicSharedMemorySize, HSMEM);
    cudaFuncSetAttribute(hgemm<2,true,false,true,false>, cudaFuncAttributeMaxDynamicSharedMemorySize, HSMEM);
    cudaFuncSetAttribute(hgemm<1,false,false,true,false>,cudaFuncAttributeMaxDynamicSharedMemorySize, HSMEM);
    cudaFuncSetAttribute(hgemm_rel,                      cudaFuncAttributeMaxDynamicSharedMemorySize, HSMEM);

    cudaStream_t s2;
    cudaStreamCreateWithFlags(&s2, cudaStreamNonBlocking);
    cudaEvent_t e1, e2, e3, e4;
    cudaEventCreateWithFlags(&e1, cudaEventDisableTiming);
    cudaEventCreateWithFlags(&e2, cudaEventDisableTiming);
    cudaEventCreateWithFlags(&e3, cudaEventDisableTiming);
    cudaEventCreateWithFlags(&e4, cudaEventDisableTiming);

    // --- s2: independent weight conversions start immediately ---
    f2h_kernel<<<(8*DD*HH/4 + 255)/256, 256, 0, s2>>>(W_rel, Wrelh, 8*DD*HH);
    f2h_kernel<<<(DHE*DHE/4 + 255)/256, 256, 0, s2>>>(W_match, Wmh, DHE*DHE);
    f2h_kernel<<<(DHE*HH/4 + 255)/256, 256, 0, s2>>>(W_lin, Wlinh, DHE*HH);

    // --- stream 0: activation transpose, fused weights, partition ---
    make_x_kernel<<<NTOT, 256>>>(features);
    build_wcat<<<(HH*HH + 255)/256, 256>>>(W_nbr, W_self);
    build_wpr<<<(DD*PRN + 255)/256, 256>>>(Wscalar, W_root, b_rgcn);
    part_count<<<(MTILES*128 + 255)/256, 256>>>(speakers);
    part_meta<<<1, 1>>>();
    part_assign<<<(NTOT + 255)/256, 256>>>(speakers);

    // fork: rel GEMM on s2
    cudaEventRecord(e1, 0);
    cudaStreamWaitEvent(s2, e1, 0);
    hgemm_rel<<<dim3(HH/128, MTILES, 4), 256, HSMEM, s2>>>();
    cudaEventRecord(e2, s2);

    // 1. [P | root] = em[:, :1024] @ Wprh + [0|b_rgcn]
    hgemm<0,false,true,true,false><<<dim3(PRN/128, NTOT/128), 256, HSMEM>>>(
        emh, Wprh, PR, nullptr, b768, DD, DHE, PRN, PRN, 0, 0, 0, 0);

    // 2. edge softmax
    edge_softmax_kernel<<<BB, 256>>>();

    cudaStreamWaitEvent(0, e2, 0);

    // 3. RGCN aggregation; neighbor window
    rgcn_agg_kernel<<<NTOT, 512>>>(speakers);
    nbr_kernel<<<dim3(BB, LSEQ/64), 512>>>();

    // 4. h2 = cath @ Wcath + b_gc -> emh upper
    hgemm<0,false,true,false,true><<<dim3(HH/128, NTOT/128), 256, HSMEM>>>(
        cath, Wcath, nullptr, emh + DD, b_gc, CATK, CATK, HH, 0, DHE, 0, 0, 0);

    // fork: EmWh = emh @ Wlinh + b_lin on s2 (overlaps XT + S + softmax)
    cudaEventRecord(e3, 0);
    cudaStreamWaitEvent(s2, e3, 0);
    hgemm<0,false,true,false,true><<<dim3(HH/128, NTOT/128), 256, HSMEM, s2>>>(
        emh, Wlinh, nullptr, EmWh, b_lin, DHE, DHE, HH, 0, HH, 0, 0, 0);
    cudaEventRecord(e4, s2);

    // 5. XTh = emh @ Wmh + b_match
    hgemm<0,false,true,false,true><<<dim3(DHE/128, NTOT/128), 256, HSMEM>>>(
        emh, Wmh, nullptr, XTh, b_match, DHE, DHE, DHE, 0, DHE, 0, 0, 0);

    // 6. S = tanh(XTh @ emh^T) batched; softmax
    hgemm<2,true,false,true,false><<<dim3(LSEQ/128, LSEQ/128, BB), 256, HSMEM>>>(
        XTh, emh, S, nullptr, nullptr, DHE, DHE, DHE, LSEQ, 0,
        (long long)LSEQ*DHE, (long long)LSEQ*DHE, (long long)LSEQ*LSEQ);
    softmax_rows_kernel<<<BB*LSEQ, 256>>>();

    // join EmWh
    cudaStreamWaitEvent(0, e4, 0);

    // 7. HID = relu(Sh @ EmWh) batched (K=256)
    hgemm<1,false,false,true,false><<<dim3(HH/128, LSEQ/128, BB), 256, HSMEM>>>(
        Sh, EmWh, HID, nullptr, nullptr, LSEQ, LSEQ, HH, HH, 0,
        (long long)LSEQ*LSEQ, (long long)LSEQ*HH, (long long)LSEQ*HH);

    // 8. output
    final_kernel<<<(NTOT*32 + 127)/128, 128>>>(W_fc, b_fc, out);
}

// round 17
// speedup vs baseline: 1.3036x; 1.0208x over previous
#include <cuda_runtime.h>
#include <cuda_fp16.h>
#include <math.h>
#include <stdint.h>

#define LSEQ 256
#define BB   64
#define DD   1024
#define HH   512
#define CC   6
#define NTOT 16384
#define DHE  1536
#define WINR 10
#define WSZ  21
#define HA4_COLS 2048
#define MTILES 129
#define CATK 1024
#define PRN  768

// ---------------- scratch ----------------
__device__ __align__(256) float g_PR  [(size_t)NTOT * PRN];
__device__ __align__(256) float g_EW  [(size_t)BB * LSEQ * WSZ];
__device__ __align__(256) float g_S   [(size_t)BB * LSEQ * LSEQ];
__device__ __align__(256) float g_HID [(size_t)NTOT * HH];
__device__ __align__(256) float g_bias768[PRN];
// fp16
__device__ __align__(256) __half g_HA4h[(size_t)NTOT * HA4_COLS];
__device__ __align__(256) __half g_cath[(size_t)NTOT * CATK];
__device__ __align__(256) __half g_emh [(size_t)NTOT * DHE];
__device__ __align__(256) __half g_XTh [(size_t)NTOT * DHE];
__device__ __align__(256) __half g_Sh  [(size_t)BB * LSEQ * LSEQ];
__device__ __align__(256) __half g_EmWh[(size_t)NTOT * HH];
__device__ __align__(256) __half g_Wprh [(size_t)DD * PRN];
__device__ __align__(256) __half g_Wrelh[(size_t)8 * DD * HH];
__device__ __align__(256) __half g_Wcath[(size_t)CATK * HH];
__device__ __align__(256) __half g_Wmh  [(size_t)DHE * DHE];
__device__ __align__(256) __half g_Wlinh[(size_t)DHE * HH];

__device__ int g_cnt[2], g_cnt2[2], g_meta[4], g_idx[MTILES * 128];

__device__ __forceinline__ void cp16(uint32_t d, const void* s) {
    asm volatile("cp.async.cg.shared.global [%0], [%1], 16;" :: "r"(d), "l"(s));
}
__device__ __forceinline__ void ldm4(uint32_t* r, uint32_t a) {
    asm volatile("ldmatrix.sync.aligned.m8n8.x4.shared.b16 {%0,%1,%2,%3}, [%4];"
                 : "=r"(r[0]), "=r"(r[1]), "=r"(r[2]), "=r"(r[3]) : "r"(a));
}
__device__ __forceinline__ void ldm4t(uint32_t* r, uint32_t a) {
    asm volatile("ldmatrix.sync.aligned.m8n8.x4.trans.shared.b16 {%0,%1,%2,%3}, [%4];"
                 : "=r"(r[0]), "=r"(r[1]), "=r"(r[2]), "=r"(r[3]) : "r"(a));
}
__device__ __forceinline__ void mma16816(float* c, const uint32_t* a, const uint32_t* b) {
    asm volatile("mma.sync.aligned.m16n8k16.row.col.f32.f16.f16.f32 "
        "{%0,%1,%2,%3}, {%4,%5,%6,%7}, {%8,%9}, {%0,%1,%2,%3};"
        : "+f"(c[0]), "+f"(c[1]), "+f"(c[2]), "+f"(c[3])
        : "r"(a[0]), "r"(a[1]), "r"(a[2]), "r"(a[3]), "r"(b[0]), "r"(b[1]));
}

// ================= fp16 hgemm: 128x128 tile, BK=32, 5-stage =================
#define HAP  40
#define HBPK 136
#define HSTG 5120
#define HNST 5
#define HSMEM (2 * HNST * HSTG * 2)   // 102400

template<bool BT>
__device__ __forceinline__ void slab_h(uint32_t ab, uint32_t bb, int wm, int wn,
                                       int lane, float acc[4][4][4])
{
    const int lr = lane & 15;
    const int lc = (lane >> 4) << 3;
    #pragma unroll
    for (int ks = 0; ks < 32; ks += 16) {
        uint32_t af[4][4], bf[4][2];
        #pragma unroll
        for (int mt = 0; mt < 4; mt++)
            ldm4(af[mt], ab + (uint32_t)(((wm * 64 + mt * 16 + lr) * HAP + ks + lc) * 2));
        #pragma unroll
        for (int np = 0; np < 2; np++) {
            uint32_t r[4];
            if (!BT)
                ldm4t(r, bb + (uint32_t)(((ks + lr) * HBPK + wn * 32 + np * 16 + lc) * 2));
            else
                ldm4(r, bb + (uint32_t)(((wn * 32 + np * 16 + (lane >> 4) * 8 + (lane & 7)) * HAP
                                          + ks + (lane & 8)) * 2));
            bf[2*np][0]   = r[0]; bf[2*np][1]   = r[1];
            bf[2*np+1][0] = r[2]; bf[2*np+1][1] = r[3];
        }
        #pragma unroll
        for (int mt = 0; mt < 4; mt++)
            #pragma unroll
            for (int nt = 0; nt < 4; nt++)
                mma16816(acc[mt][nt], af[mt], bf[nt]);
    }
}

// ACT: 0 none, 1 relu, 2 tanh, 3 exp(tanh)
template<int ACT, bool BT, bool BIAS, bool WF, bool WH>
__global__ __launch_bounds__(256, 2) void hgemm(
    const __half* __restrict__ A, const __half* __restrict__ B,
    float* __restrict__ Cf, __half* __restrict__ Ch, const float* __restrict__ bias,
    int K, int lda, int ldb, int ldcf, int ldch,
    long long zA, long long zB, long long zC)
{
    A += (long long)blockIdx.z * zA;
    B += (long long)blockIdx.z * zB;
    if (WF) Cf += (long long)blockIdx.z * zC;
    if (WH) Ch += (long long)blockIdx.z * zC;

    extern __shared__ __half smh[];
    const uint32_t asb = (uint32_t)__cvta_generic_to_shared(smh);
    const uint32_t bsb = (uint32_t)__cvta_generic_to_shared(smh + HNST * HSTG);

    const int tid = threadIdx.x, lane = tid & 31, wid = tid >> 5;
    const int wm = wid & 1, wn = wid >> 1, g = lane >> 2, t = lane & 3;
    const int m0 = blockIdx.y * 128, n0 = blockIdx.x * 128;

    const int ar = tid >> 1, ac = (tid & 1) * 16;
    const int bkr = tid >> 4, bnc = (tid & 15) * 8;

    float acc[4][4][4];
    #pragma unroll
    for (int i = 0; i < 4; i++)
        #pragma unroll
        for (int j = 0; j < 4; j++)
            #pragma unroll
            for (int e = 0; e < 4; e++) acc[i][j][e] = 0.f;

    const int KT = K / 32;
    auto fill = [&](int s, int k0) {
        const uint32_t ab = asb + (uint32_t)(s * HSTG * 2);
        cp16(ab + (ar * HAP + ac) * 2,     A + (long long)(m0 + ar) * lda + k0 + ac);
        cp16(ab + (ar * HAP + ac + 8) * 2, A + (long long)(m0 + ar) * lda + k0 + ac + 8);
        const uint32_t bb = bsb + (uint32_t)(s * HSTG * 2);
        if (!BT) {
            cp16(bb + (bkr * HBPK + bnc) * 2,        B + (long long)(k0 + bkr) * ldb + n0 + bnc);
            cp16(bb + ((bkr + 16) * HBPK + bnc) * 2, B + (long long)(k0 + bkr + 16) * ldb + n0 + bnc);
        } else {
            cp16(bb + (ar * HAP + ac) * 2,     B + (long long)(n0 + ar) * ldb + k0 + ac);
            cp16(bb + (ar * HAP + ac + 8) * 2, B + (long long)(n0 + ar) * ldb + k0 + ac + 8);
        }
    };

    fill(0, 0);   asm volatile("cp.async.commit_group;");
    fill(1, 32);  asm volatile("cp.async.commit_group;");
    fill(2, 64);  asm volatile("cp.async.commit_group;");
    fill(3, 96);  asm volatile("cp.async.commit_group;");

    int s = 0, sp = 4;
    for (int kt = 0; kt < KT; kt++) {
        asm volatile("cp.async.wait_group 3;" ::: "memory");
        __syncthreads();
        if (kt + 4 < KT) fill(sp, (kt + 4) * 32);
        asm volatile("cp.async.commit_group;");
        slab_h<BT>(asb + (uint32_t)((s * HSTG) * 2),
                   bsb + (uint32_t)((s * HSTG) * 2), wm, wn, lane, acc);
        if (++s == HNST) s = 0;
        if (++sp == HNST) sp = 0;
    }

    #pragma unroll
    for (int mt = 0; mt < 4; mt++)
        #pragma unroll
        for (int nt = 0; nt < 4; nt++) {
            const int col = n0 + wn * 32 + nt * 8 + t * 2;
            #pragma unroll
            for (int half = 0; half < 2; half++) {
                const long long row = m0 + wm * 64 + mt * 16 + g + half * 8;
                float v0 = acc[mt][nt][half * 2 + 0];
                float v1 = acc[mt][nt][half * 2 + 1];
                if (BIAS) { v0 += bias[col]; v1 += bias[col + 1]; }
                if (ACT == 1) { v0 = fmaxf(v0, 0.f); v1 = fmaxf(v1, 0.f); }
                if (ACT == 2) { v0 = tanhf(v0); v1 = tanhf(v1); }
                if (ACT == 3) { v0 = __expf(tanhf(v0)); v1 = __expf(tanhf(v1)); }
                if (WF) *(float2*)(Cf + row * ldcf + col) = make_float2(v0, v1);
                if (WH) {
                    __half2 h; h.x = __float2half(v0); h.y = __float2half(v1);
                    *(__half2*)(Ch + row * ldch + col) = h;
                }
            }
        }
}

// speaker-split relation fp16 GEMM (A rows gathered from g_emh[:, :1024])
__global__ __launch_bounds__(256, 2) void hgemm_rel()
{
    const int M0 = g_meta[0], M0pad = g_meta[1], M1 = g_meta[2], M1pad = g_meta[3];
    const int m0 = blockIdx.y * 128;
    if (m0 >= M0pad + M1pad) return;
    const int grp = (m0 < M0pad) ? 0 : 1;
    const int n0 = blockIdx.x * 128, j = blockIdx.z;

    extern __shared__ __half smh[];
    __shared__ int sidx[128];
    const uint32_t asb = (uint32_t)__cvta_generic_to_shared(smh);
    const uint32_t bsb = (uint32_t)__cvta_generic_to_shared(smh + HNST * HSTG);

    const int tid = threadIdx.x, lane = tid & 31, wid = tid >> 5;
    const int wm = wid & 1, wn = wid >> 1, g = lane >> 2, t = lane & 3;

    if (tid < 128) sidx[tid] = g_idx[m0 + tid];

    const int ar = tid >> 1, ac = (tid & 1) * 16;
    const int bkr = tid >> 4, bnc = (tid & 15) * 8;
    const __half* Arow = g_emh + (long long)g_idx[m0 + ar] * DHE;
    const __half* B = g_Wrelh + (long long)(grp * 4 + j) * DD * HH;

    float acc[4][4][4];
    #pragma unroll
    for (int i = 0; i < 4; i++)
        #pragma unroll
        for (int jj = 0; jj < 4; jj++)
            #pragma unroll
            for (int e = 0; e < 4; e++) acc[i][jj][e] = 0.f;

    auto fill = [&](int s, int k0) {
        const uint32_t ab = asb + (uint32_t)(s * HSTG * 2);
        cp16(ab + (ar * HAP + ac) * 2,     Arow + k0 + ac);
        cp16(ab + (ar * HAP + ac + 8) * 2, Arow + k0 + ac + 8);
        const uint32_t bb = bsb + (uint32_t)(s * HSTG * 2);
        cp16(bb + (bkr * HBPK + bnc) * 2,        B + (long long)(k0 + bkr) * HH + n0 + bnc);
        cp16(bb + ((bkr + 16) * HBPK + bnc) * 2, B + (long long)(k0 + bkr + 16) * HH + n0 + bnc);
    };

    fill(0, 0);   asm volatile("cp.async.commit_group;");
    fill(1, 32);  asm volatile("cp.async.commit_group;");
    fill(2, 64);  asm volatile("cp.async.commit_group;");
    fill(3, 96);  asm volatile("cp.async.commit_group;");

    const int KT = DD / 32;
    int s = 0, sp = 4;
    for (int kt = 0; kt < KT; kt++) {
        asm volatile("cp.async.wait_group 3;" ::: "memory");
        __syncthreads();
        if (kt + 4 < KT) fill(sp, (kt + 4) * 32);
        asm volatile("cp.async.commit_group;");
        slab_h<false>(asb + (uint32_t)((s * HSTG) * 2),
                      bsb + (uint32_t)((s * HSTG) * 2), wm, wn, lane, acc);
        if (++s == HNST) s = 0;
        if (++sp == HNST) sp = 0;
    }

    #pragma unroll
    for (int mt = 0; mt < 4; mt++)
        #pragma unroll
        for (int nt = 0; nt < 4; nt++) {
            const int col = j * HH + n0 + wn * 32 + nt * 8 + t * 2;
            #pragma unroll
            for (int half = 0; half < 2; half++) {
                const int lr = wm * 64 + mt * 16 + g + half * 8;
                const int pr = m0 + lr;
                const bool valid = (grp == 0) ? (pr < M0) : (pr - M0pad < M1);
                if (valid) {
                    __half2 h;
                    h.x = __float2half(acc[mt][nt][half * 2]);
                    h.y = __float2half(acc[mt][nt][half * 2 + 1]);
                    *(__half2*)(g_HA4h + (long long)sidx[lr] * HA4_COLS + col) = h;
                }
            }
        }
}

// ================= glue =================
__global__ void part_count(const int* __restrict__ sp)
{
    const int n = blockIdx.x * blockDim.x + threadIdx.x;
    if (n < MTILES * 128) g_idx[n] = 0;
    if (n < NTOT) atomicAdd(&g_cnt[sp[(n & 255) * BB + (n >> 8)]], 1);
}
__global__ void part_meta()
{
    const int M0 = g_cnt[0], M1 = g_cnt[1];
    g_meta[0] = M0; g_meta[1] = ((M0 + 127) / 128) * 128;
    g_meta[2] = M1; g_meta[3] = ((M1 + 127) / 128) * 128;
    g_cnt[0] = g_cnt[1] = g_cnt2[0] = g_cnt2[1] = 0;
}
__global__ void part_assign(const int* __restrict__ sp)
{
    const int n = blockIdx.x * blockDim.x + threadIdx.x;
    if (n >= NTOT) return;
    const int s = sp[(n & 255) * BB + (n >> 8)];
    const int slot = atomicAdd(&g_cnt2[s], 1);
    g_idx[(s == 0) ? slot : g_meta[1] + slot] = n;
}
__global__ void f2h_kernel(const float* __restrict__ s, __half* __restrict__ d, int n)
{
    int i = (blockIdx.x * blockDim.x + threadIdx.x) * 4;
    if (i + 3 < n) {
        float4 v = *(const float4*)(s + i);
        __half2 a, b;
        a.x = __float2half(v.x); a.y = __float2half(v.y);
        b.x = __float2half(v.z); b.y = __float2half(v.w);
        *(__half2*)(d + i) = a;
        *(__half2*)(d + i + 2) = b;
    }
}
__global__ void make_x_kernel(const float* __restrict__ f)
{
    const int n = blockIdx.x, b = n >> 8, s = n & 255;
    const float* src = f + ((long long)s * BB + b) * DD;
    for (int d = threadIdx.x; d < DD; d += blockDim.x)
        g_emh[(long long)n * DHE + d] = __float2half(src[d]);
}
__global__ void build_wcat(const float* __restrict__ Wn, const float* __restrict__ Ws)
{
    const int i = blockIdx.x * blockDim.x + threadIdx.x;
    if (i < HH * HH) {
        g_Wcath[i] = __float2half(Wn[i]);
        g_Wcath[HH * HH + i] = __float2half(Ws[i]);
    }
}
__global__ void build_wpr(const float* __restrict__ Ws, const float* __restrict__ Wr,
                          const float* __restrict__ br)
{
    const int i = blockIdx.x * blockDim.x + threadIdx.x;
    if (i < DD * PRN) {
        const int d = i / PRN, c = i % PRN;
        g_Wprh[i] = __float2half((c < 256) ? Ws[d * 256 + c] : Wr[d * 512 + (c - 256)]);
    }
    if (i < PRN) g_bias768[i] = (i < 256) ? 0.f : br[i - 256];
}
// 2-pass edge softmax (no max pass; |P| small so exp is safe)
__global__ __launch_bounds__(256) void edge_softmax_kernel()
{
    const int b = blockIdx.x;
    const int i = threadIdx.x;
    const float* Pb = g_PR + (long long)b * 256 * PRN;

    float Z = 0.f;
    for (int s = 0; s < LSEQ; s++)
        Z += __expf(Pb[(long long)s * PRN + i]);

    float ew[WSZ];
    float Swin = 0.f;
    #pragma unroll
    for (int d = 0; d < WSZ; d++) {
        const int s = i - WINR + d;
        float e = 0.f;
        if (s >= 0 && s < LSEQ) {
            e = __expf(Pb[(long long)s * PRN + i]);
            Swin += e;
        }
        ew[d] = e;
    }
    const float den = Swin + 1e-10f * (Z - Swin);
    float* dst = g_EW + ((long long)(b * 256 + i)) * WSZ;
    #pragma unroll
    for (int d = 0; d < WSZ; d++)
        dst[d] = ew[d] / den;
}
__global__ __launch_bounds__(512) void rgcn_agg_kernel(const int* __restrict__ sp)
{
    const int n = blockIdx.x, b = n >> 8, k = n & 255, h = threadIdx.x;
    __shared__ float w[WSZ];
    const int lo = max(k - WINR, 0), hi = min(k + WINR, LSEQ - 1);
    const int cnt = hi - lo + 1;
    if (h < cnt) {
        const int i = lo + h;
        w[h] = g_EW[((long long)(b * 256 + i)) * WSZ + (k - i + WINR)];
    }
    __syncthreads();
    const int spk = sp[k * BB + b];
    float acc = g_PR[(long long)n * PRN + 256 + h];
    for (int t = 0; t < cnt; t++) {
        const int i = lo + t;
        const int j = spk * 2 + ((i < k) ? 0 : 1);
        acc += w[t] * __half2float(g_HA4h[((long long)(b * 256 + i)) * HA4_COLS + j * HH + h]);
    }
    g_cath[(long long)n * CATK + HH + h] = __float2half(acc);
}
// sliding window over fp16 h1 (cath upper) -> fp16 cath lower
__global__ __launch_bounds__(512) void nbr_kernel()
{
    const int b = blockIdx.x, ks = blockIdx.y * 64, h = threadIdx.x;
    float run = 0.f;
    const int lo = max(ks - WINR, 0), hi = min(ks + WINR, LSEQ - 1);
    for (int j = lo; j <= hi; j++)
        run += __half2float(g_cath[((long long)(b * 256 + j)) * CATK + HH + h]);
    g_cath[((long long)(b * 256 + ks)) * CATK + h] = __float2half(run);
    for (int k = ks + 1; k < ks + 64; k++) {
        if (k + WINR < LSEQ)
            run += __half2float(g_cath[((long long)(b * 256 + k + WINR)) * CATK + HH + h]);
        if (k - WINR - 1 >= 0)
            run -= __half2float(g_cath[((long long)(b * 256 + k - WINR - 1)) * CATK + HH + h]);
        g_cath[((long long)(b * 256 + k)) * CATK + h] = __float2half(run);
    }
}
// one-pass row normalize: S already holds exp(tanh(.)) fp32
__global__ void softmax_rows_kernel()
{
    __shared__ float red[256];
    const long long r = blockIdx.x;
    const int s = threadIdx.x;
    const float e = g_S[r * 256 + s];
    red[s] = e; __syncthreads();
    for (int o = 128; o > 0; o >>= 1) { if (s < o) red[s] += red[s + o]; __syncthreads(); }
    g_Sh[r * 256 + s] = __float2half(e / red[0]);
}
__global__ void final_kernel(const float* __restrict__ W_fc,
                             const float* __restrict__ b_fc, float* __restrict__ out)
{
    const int gw = (blockIdx.x * blockDim.x + threadIdx.x) >> 5;
    const int lane = threadIdx.x & 31;
    if (gw >= NTOT) return;
    float p[CC] = {0.f, 0.f, 0.f, 0.f, 0.f, 0.f};
    #pragma unroll
    for (int j = 0; j < 16; j++) {
        const int hx = lane + j * 32;
        const float hv = g_HID[(long long)gw * HH + hx];
        const float* wr = W_fc + (long long)hx * CC;
        #pragma unroll
        for (int c = 0; c < CC; c++) p[c] += hv * wr[c];
    }
    #pragma unroll
    for (int o = 16; o > 0; o >>= 1)
        #pragma unroll
        for (int c = 0; c < CC; c++) p[c] += __shfl_down_sync(0xffffffffu, p[c], o);
    if (lane == 0) {
        float lg[CC], m = -1e30f;
        #pragma unroll
        for (int c = 0; c < CC; c++) { lg[c] = p[c] + b_fc[c]; m = fmaxf(m, lg[c]); }
        float ss = 0.f;
        #pragma unroll
        for (int c = 0; c < CC; c++) ss += __expf(lg[c] - m);
        const float lse = m + logf(ss);
        #pragma unroll
        for (int c = 0; c < CC; c++) out[(long long)gw * CC + c] = lg[c] - lse;
    }
}

// ================= host =================
extern "C" void kernel_launch(void* const* d_in, const int* in_sizes, int n_in,
                              void* d_out, int out_size)
{
    const float* features = (const float*)d_in[0];
    const float* Wscalar  = (const float*)d_in[1];
    const float* W_rel    = (const float*)d_in[2];
    const float* W_root   = (const float*)d_in[3];
    const float* b_rgcn   = (const float*)d_in[4];
    const float* W_nbr    = (const float*)d_in[5];
    const float* W_self   = (const float*)d_in[6];
    const float* b_gc     = (const float*)d_in[7];
    const float* W_match  = (const float*)d_in[8];
    const float* b_match  = (const float*)d_in[9];
    const float* W_lin    = (const float*)d_in[10];
    const float* b_lin    = (const float*)d_in[11];
    const float* W_fc     = (const float*)d_in[12];
    const float* b_fc     = (const float*)d_in[13];
    const int*   speakers = (const int*)  d_in[14];
    float* out = (float*)d_out;

    float *PR, *S, *HID, *b768;
    __half *emh, *cath, *XTh, *Sh, *EmWh, *Wprh, *Wrelh, *Wcath, *Wmh, *Wlinh;
    cudaGetSymbolAddress((void**)&PR,  g_PR);
    cudaGetSymbolAddress((void**)&S,   g_S);
    cudaGetSymbolAddress((void**)&HID, g_HID);
    cudaGetSymbolAddress((void**)&b768,g_bias768);
    cudaGetSymbolAddress((void**)&emh, g_emh);
    cudaGetSymbolAddress((void**)&cath,g_cath);
    cudaGetSymbolAddress((void**)&XTh, g_XTh);
    cudaGetSymbolAddress((void**)&Sh,  g_Sh);
    cudaGetSymbolAddress((void**)&EmWh,g_EmWh);
    cudaGetSymbolAddress((void**)&Wprh, g_Wprh);
    cudaGetSymbolAddress((void**)&Wrelh,g_Wrelh);
    cudaGetSymbolAddress((void**)&Wcath,g_Wcath);
    cudaGetSymbolAddress((void**)&Wmh,  g_Wmh);
    cudaGetSymbolAddress((void**)&Wlinh,g_Wlinh);

    cudaFuncSetAttribute(hgemm<0,false,true,true,false>, cudaFuncAttributeMaxDynamicSharedMemorySize, HSMEM);
    cudaFuncSetAttribute(hgemm<0,false,true,false,true>, cudaFuncAttributeMaxDynamicSharedMemorySize, HSMEM);
    cudaFuncSetAttribute(hgemm<3,true,false,true,false>, cudaFuncAttributeMaxDynamicSharedMemorySize, HSMEM);
    cudaFuncSetAttribute(hgemm<1,false,false,true,false>,cudaFuncAttributeMaxDynamicSharedMemorySize, HSMEM);
    cudaFuncSetAttribute(hgemm_rel,                      cudaFuncAttributeMaxDynamicSharedMemorySize, HSMEM);

    cudaStream_t s2;
    cudaStreamCreateWithFlags(&s2, cudaStreamNonBlocking);
    cudaEvent_t e1, e2, e3, e4;
    cudaEventCreateWithFlags(&e1, cudaEventDisableTiming);
    cudaEventCreateWithFlags(&e2, cudaEventDisableTiming);
    cudaEventCreateWithFlags(&e3, cudaEventDisableTiming);
    cudaEventCreateWithFlags(&e4, cudaEventDisableTiming);

    // --- s2: independent weight conversions start immediately ---
    f2h_kernel<<<(8*DD*HH/4 + 255)/256, 256, 0, s2>>>(W_rel, Wrelh, 8*DD*HH);
    f2h_kernel<<<(DHE*DHE/4 + 255)/256, 256, 0, s2>>>(W_match, Wmh, DHE*DHE);
    f2h_kernel<<<(DHE*HH/4 + 255)/256, 256, 0, s2>>>(W_lin, Wlinh, DHE*HH);

    // --- stream 0: activation transpose, fused weights, partition ---
    make_x_kernel<<<NTOT, 256>>>(features);
    build_wcat<<<(HH*HH + 255)/256, 256>>>(W_nbr, W_self);
    build_wpr<<<(DD*PRN + 255)/256, 256>>>(Wscalar, W_root, b_rgcn);
    part_count<<<(MTILES*128 + 255)/256, 256>>>(speakers);
    part_meta<<<1, 1>>>();
    part_assign<<<(NTOT + 255)/256, 256>>>(speakers);

    // fork: rel GEMM on s2
    cudaEventRecord(e1, 0);
    cudaStreamWaitEvent(s2, e1, 0);
    hgemm_rel<<<dim3(HH/128, MTILES, 4), 256, HSMEM, s2>>>();
    cudaEventRecord(e2, s2);

    // 1. [P | root] = em[:, :1024] @ Wprh + [0|b_rgcn]
    hgemm<0,false,true,true,false><<<dim3(PRN/128, NTOT/128), 256, HSMEM>>>(
        emh, Wprh, PR, nullptr, b768, DD, DHE, PRN, PRN, 0, 0, 0, 0);

    // 2. edge softmax (2-pass)
    edge_softmax_kernel<<<BB, 256>>>();

    cudaStreamWaitEvent(0, e2, 0);

    // 3. RGCN aggregation; neighbor window (fp16 shadow only)
    rgcn_agg_kernel<<<NTOT, 512>>>(speakers);
    nbr_kernel<<<dim3(BB, LSEQ/64), 512>>>();

    // 4. h2 = cath @ Wcath + b_gc -> emh upper
    hgemm<0,false,true,false,true><<<dim3(HH/128, NTOT/128), 256, HSMEM>>>(
        cath, Wcath, nullptr, emh + DD, b_gc, CATK, CATK, HH, 0, DHE, 0, 0, 0);

    // fork: EmWh = emh @ Wlinh + b_lin on s2 (overlaps XT + S + softmax)
    cudaEventRecord(e3, 0);
    cudaStreamWaitEvent(s2, e3, 0);
    hgemm<0,false,true,false,true><<<dim3(HH/128, NTOT/128), 256, HSMEM, s2>>>(
        emh, Wlinh, nullptr, EmWh, b_lin, DHE, DHE, HH, 0, HH, 0, 0, 0);
    cudaEventRecord(e4, s2);

    // 5. XTh = emh @ Wmh + b_match
    hgemm<0,false,true,false,true><<<dim3(DHE/128, NTOT/128), 256, HSMEM>>>(
        emh, Wmh, nullptr, XTh, b_match, DHE, DHE, DHE, 0, DHE, 0, 0, 0);

    // 6. S = exp(tanh(XTh @ emh^T)) batched; one-pass row normalize
    hgemm<3,true,false,true,false><<<dim3(LSEQ/128, LSEQ/128, BB), 256, HSMEM>>>(
        XTh, emh, S, nullptr, nullptr, DHE, DHE, DHE, LSEQ, 0,
        (long long)LSEQ*DHE, (long long)LSEQ*DHE, (long long)LSEQ*LSEQ);
    softmax_rows_kernel<<<BB*LSEQ, 256>>>();

    // join EmWh
    cudaStreamWaitEvent(0, e4, 0);

    // 7. HID = relu(Sh @ EmWh) batched (K=256)
    hgemm<1,false,false,true,false><<<dim3(HH/128, LSEQ/128, BB), 256, HSMEM>>>(
        Sh, EmWh, HID, nullptr, nullptr, LSEQ, LSEQ, HH, HH, 0,
        (long long)LSEQ*LSEQ, (long long)LSEQ*HH, (long long)LSEQ*HH);

    // 8. output
    final_kernel<<<(NTOT*32 + 127)/128, 128>>>(W_fc, b_fc, out);
}